// round 8
// baseline (speedup 1.0000x reference)
#include <cuda_runtime.h>
#include <cstdint>

#define BB 64
#define NS 512
#define DS 300
#define DP 320                          // K padded to %32
#define BN_ROWS (BB*NS)                 // 32768
#define INV_SQRT_D 0.057735026918962576f
#define MASKED_CNORM (1.0f)

// ---------------------------------------------------------------------------
// Device-global scratch (runtime allocation forbidden)
// ---------------------------------------------------------------------------
__device__ alignas(1024) signed char g_c8h[(size_t)BN_ROWS * DP];
__device__ alignas(1024) signed char g_c8l[(size_t)BN_ROWS * DP];
__device__ alignas(1024) signed char g_o8h[(size_t)BN_ROWS * DP];
__device__ alignas(1024) signed char g_o8l[(size_t)BN_ROWS * DP];
__device__ alignas(1024) signed char g_ct8h[(size_t)BB * DS * NS];  // concepts^T [b][d][m]
__device__ alignas(1024) signed char g_ct8l[(size_t)BB * DS * NS];
__device__ alignas(1024) signed char g_wq8h[DS * DP];
__device__ alignas(1024) signed char g_wq8l[DS * DP];
__device__ alignas(1024) signed char g_wk8h[DS * DP];
__device__ alignas(1024) signed char g_wk8l[DS * DP];
__device__ alignas(1024) signed char g_q8h[(size_t)BN_ROWS * DP];
__device__ alignas(1024) signed char g_q8l[(size_t)BN_ROWS * DP];
__device__ alignas(1024) signed char g_k8h[(size_t)BN_ROWS * DP];
__device__ alignas(1024) signed char g_k8l[(size_t)BN_ROWS * DP];
__device__ alignas(1024) signed char g_p8h[(size_t)BB * NS * NS];
__device__ alignas(1024) signed char g_p8l[(size_t)BB * NS * NS];
__device__ alignas(1024) float g_A[(size_t)BB * NS * NS];     // ct fp32 scratch, then scores
__device__ alignas(1024) float g_T[(size_t)BN_ROWS * DS];     // Q fp32
__device__ alignas(1024) float g_U[(size_t)BN_ROWS * DS];     // K fp32
__device__ alignas(1024) float g_S[(size_t)BN_ROWS * DS];     // semantic fp32
__device__ float g_sC[BN_ROWS];
__device__ float g_sO[BN_ROWS];
__device__ float g_sWq[DS];
__device__ float g_sWk[DS];
__device__ float g_sQ[BN_ROWS];
__device__ float g_sK[BN_ROWS];
__device__ float g_sP[BN_ROWS];
__device__ float g_sCt[BB * DS];

// ---------------------------------------------------------------------------
// PTX helpers (sm_80-era only; compiles under compute_103)
// ---------------------------------------------------------------------------
__device__ __forceinline__ uint32_t smem_to_u32(const void* p) {
    uint32_t a;
    asm("{ .reg .u64 t; cvta.to.shared.u64 t, %1; cvt.u32.u64 %0, t; }" : "=r"(a) : "l"(p));
    return a;
}
__device__ __forceinline__ void cp_async16(uint32_t dst, const void* src, int src_bytes) {
    asm volatile("cp.async.cg.shared.global [%0], [%1], 16, %2;"
                 :: "r"(dst), "l"(src), "r"(src_bytes) : "memory");
}
#define CP_COMMIT() asm volatile("cp.async.commit_group;" ::: "memory")
#define CP_WAIT(n)  asm volatile("cp.async.wait_group %0;" :: "n"(n) : "memory")

__device__ __forceinline__ void ldsm_x4(uint32_t* r, uint32_t addr) {
    asm volatile("ldmatrix.sync.aligned.m8n8.x4.shared.b16 {%0,%1,%2,%3}, [%4];"
                 : "=r"(r[0]), "=r"(r[1]), "=r"(r[2]), "=r"(r[3]) : "r"(addr));
}
// s32 += s8[16x32] x s8[32x8]
__device__ __forceinline__ void mma_s8(int* d, const uint32_t* a, const uint32_t* b) {
    asm volatile("mma.sync.aligned.m16n8k32.row.col.s32.s8.s8.s32 "
                 "{%0,%1,%2,%3}, {%4,%5,%6,%7}, {%8,%9}, {%0,%1,%2,%3};"
                 : "+r"(d[0]), "+r"(d[1]), "+r"(d[2]), "+r"(d[3])
                 : "r"(a[0]), "r"(a[1]), "r"(a[2]), "r"(a[3]), "r"(b[0]), "r"(b[1]));
}

// ---------------------------------------------------------------------------
// Per-row 2-limb s8 quantization: x ~= s*(hi + lo/256), s = rowmax/127.
// src row-major ld=kin(read)/arbitrary; dst [rows x kout], pad zero.
// ---------------------------------------------------------------------------
__global__ void quant_rows_kernel(const float* __restrict__ src, int ld, int kin, int kout,
                                  signed char* __restrict__ h, signed char* __restrict__ l,
                                  float* __restrict__ sOut)
{
    __shared__ float sh[4];
    int row = blockIdx.x, tid = threadIdx.x;
    const float* x = src + (size_t)row * ld;
    float mx = 0.f;
    for (int i = tid; i < kin; i += 128) mx = fmaxf(mx, fabsf(x[i]));
#pragma unroll
    for (int o = 16; o > 0; o >>= 1) mx = fmaxf(mx, __shfl_xor_sync(0xffffffffu, mx, o));
    if ((tid & 31) == 0) sh[tid >> 5] = mx;
    __syncthreads();
    mx = fmaxf(fmaxf(sh[0], sh[1]), fmaxf(sh[2], sh[3]));
    float s = (mx > 1e-30f) ? mx * (1.0f / 127.0f) : 1.0f;
    float inv = 1.0f / s;
    if (tid == 0) sOut[row] = s;
    size_t base = (size_t)row * kout;
    for (int i = tid; i < kout; i += 128) {
        int hi = 0, lo = 0;
        if (i < kin) {
            float y = x[i] * inv;
            hi = __float2int_rn(y); hi = max(-127, min(127, hi));
            lo = __float2int_rn((y - (float)hi) * 256.0f); lo = max(-127, min(127, lo));
        }
        h[base + i] = (signed char)hi;
        l[base + i] = (signed char)lo;
    }
}

// concepts [b][m][300] -> fp32 ct [b][d][512]
__global__ void transpose_kernel(const float* __restrict__ in, float* __restrict__ outp)
{
    __shared__ float t[32][33];
    int b = blockIdx.z;
    int dBase = blockIdx.x * 32, mBase = blockIdx.y * 32;
    int tx = threadIdx.x, ty = threadIdx.y;
#pragma unroll
    for (int i = 0; i < 4; i++) {
        int m = mBase + ty + i * 8, d = dBase + tx;
        if (d < DS) t[ty + i * 8][tx] = in[((size_t)b * NS + m) * DS + d];
    }
    __syncthreads();
#pragma unroll
    for (int i = 0; i < 4; i++) {
        int d = dBase + ty + i * 8, m = mBase + tx;
        if (d < DS) outp[((size_t)b * DS + d) * NS + m] = t[tx][ty + i * 8];
    }
}

// ---------------------------------------------------------------------------
// s8 2-limb GEMM (NT): C = scale*sA[r]*sB[c]*(accH + accL/256) (+bias[c])
// CTA 128x128, BK=32, 256 thr, 8 warps (4m x 2n), warp tile 32x64.
// Tiles: 128 rows x 32B (+16B pad -> 48B stride, bank-conflict-free ldsm).
// ---------------------------------------------------------------------------
#define ROW_B   48
#define TILE_B  (128 * ROW_B)          // 6144
#define OFF_AH  0
#define OFF_AL  (1 * TILE_B)
#define OFF_BH  (2 * TILE_B)
#define OFF_BL  (3 * TILE_B)
#define STAGE_B (4 * TILE_B)           // 24576
#define NSTAGE  4
#define GEMM_SMEM (NSTAGE * STAGE_B)   // 98304

__global__ void __launch_bounds__(256, 1)
gemm_s8_kernel(const signed char* __restrict__ Ah, const signed char* __restrict__ Al,
               const signed char* __restrict__ Bh, const signed char* __restrict__ Bl,
               const float* __restrict__ sA, const float* __restrict__ sB,
               const float* __restrict__ bias, float* __restrict__ Cf,
               int M, int N, int K, int ldc,
               long long strA, long long strB, long long strC,
               long long strSA, long long strSB, float scale)
{
    extern __shared__ __align__(128) char smem[];
    uint32_t smem_base = smem_to_u32(smem);
    int tid = threadIdx.x;
    int wid = tid >> 5, lane = tid & 31;
    int wm = wid >> 1, wn = wid & 1;
    int z = blockIdx.z;
    int rowBase = blockIdx.x * 128;
    int colBase = blockIdx.y * 128;

    const signed char* pAh = Ah + (size_t)z * strA;
    const signed char* pAl = Al + (size_t)z * strA;
    const signed char* pBh = Bh + (size_t)z * strB;
    const signed char* pBl = Bl + (size_t)z * strB;
    const float* sAp = sA + (size_t)z * strSA;
    const float* sBp = sB + (size_t)z * strSB;

    int nChunks = K >> 5;

    auto prefetch = [&](int c, int stage) {
        int k0 = c << 5;
        uint32_t sb = smem_base + stage * STAGE_B;
        int row = tid >> 1, half = tid & 1;           // 256 thr = 128 rows x 2 halves
        uint32_t d = sb + row * ROW_B + half * 16;
        size_t aOff = (size_t)(rowBase + row) * K + k0 + half * 16;
        int bRow = colBase + row;
        int bOk = bRow < N;
        size_t bOff = (size_t)(bOk ? bRow : 0) * K + k0 + half * 16;
        int bBytes = bOk ? 16 : 0;
        cp_async16(d + OFF_AH, pAh + aOff, 16);
        cp_async16(d + OFF_AL, pAl + aOff, 16);
        cp_async16(d + OFF_BH, pBh + bOff, bBytes);
        cp_async16(d + OFF_BL, pBl + bOff, bBytes);
    };

    int accH[2][8][4], accL[2][8][4];
#pragma unroll
    for (int mi = 0; mi < 2; mi++)
#pragma unroll
        for (int ni = 0; ni < 8; ni++)
#pragma unroll
            for (int j = 0; j < 4; j++) { accH[mi][ni][j] = 0; accL[mi][ni][j] = 0; }

    prefetch(0, 0); CP_COMMIT();
    if (nChunks > 1) prefetch(1, 1);
    CP_COMMIT();
    if (nChunks > 2) prefetch(2, 2);
    CP_COMMIT();

#pragma unroll 1
    for (int c = 0; c < nChunks; c++) {
        if (c + 3 < nChunks) prefetch(c + 3, (c + 3) & (NSTAGE - 1));
        CP_COMMIT();
        CP_WAIT(3);
        __syncthreads();

        uint32_t sb = smem_base + (c & (NSTAGE - 1)) * STAGE_B;
        uint32_t ah[2][4], al[2][4];
#pragma unroll
        for (int mi = 0; mi < 2; mi++) {
            uint32_t addr = sb + OFF_AH +
                (uint32_t)((wm * 32 + mi * 16 + (lane & 15)) * ROW_B + (lane >> 4) * 16);
            ldsm_x4(ah[mi], addr);
            ldsm_x4(al[mi], addr + (OFF_AL - OFF_AH));
        }
        uint32_t bh[8][2], bl[8][2];
#pragma unroll
        for (int g = 0; g < 4; g++) {
            uint32_t addr = sb + OFF_BH +
                (uint32_t)((wn * 64 + g * 16 + ((lane >> 4) & 1) * 8 + (lane & 7)) * ROW_B
                           + ((lane >> 3) & 1) * 16);
            uint32_t r[4];
            ldsm_x4(r, addr);
            bh[2*g][0] = r[0]; bh[2*g][1] = r[1]; bh[2*g+1][0] = r[2]; bh[2*g+1][1] = r[3];
            ldsm_x4(r, addr + (OFF_BL - OFF_BH));
            bl[2*g][0] = r[0]; bl[2*g][1] = r[1]; bl[2*g+1][0] = r[2]; bl[2*g+1][1] = r[3];
        }
        // 3 passes, pass-major: hh -> accH ; hl, lh -> accL (exact s32)
#pragma unroll
        for (int mi = 0; mi < 2; mi++)
#pragma unroll
            for (int ni = 0; ni < 8; ni++)
                mma_s8(accH[mi][ni], ah[mi], bh[ni]);
#pragma unroll
        for (int mi = 0; mi < 2; mi++)
#pragma unroll
            for (int ni = 0; ni < 8; ni++)
                mma_s8(accL[mi][ni], ah[mi], bl[ni]);
#pragma unroll
        for (int mi = 0; mi < 2; mi++)
#pragma unroll
            for (int ni = 0; ni < 8; ni++)
                mma_s8(accL[mi][ni], al[mi], bh[ni]);
        __syncthreads();
    }

    // Dequant epilogue
    float* Cfp = Cf + (size_t)z * strC;
#pragma unroll
    for (int mi = 0; mi < 2; mi++) {
#pragma unroll
        for (int ni = 0; ni < 8; ni++) {
#pragma unroll
            for (int half = 0; half < 2; half++) {
                int gm = rowBase + wm * 32 + mi * 16 + (lane >> 2) + half * 8;
                int gn = colBase + wn * 64 + ni * 8 + 2 * (lane & 3);
                if (gn < N) {
                    float sa = sAp[gm] * scale;
                    float v0 = ((float)accH[mi][ni][2*half] +
                                (float)accL[mi][ni][2*half] * (1.0f/256.0f)) * sa * sBp[gn];
                    if (bias) v0 += bias[gn];
                    size_t o = (size_t)gm * ldc + gn;
                    Cfp[o] = v0;
                    if (gn + 1 < N) {
                        float v1 = ((float)accH[mi][ni][2*half+1] +
                                    (float)accL[mi][ni][2*half+1] * (1.0f/256.0f)) * sa * sBp[gn+1];
                        if (bias) v1 += bias[gn+1];
                        Cfp[o+1] = v1;
                    }
                }
            }
        }
    }
}

// ---------------------------------------------------------------------------
// Row softmax over N=512 -> 2-limb s8 P with per-row scale (Pmax = 1/sum)
// ---------------------------------------------------------------------------
__global__ void softmax_quant_kernel(const float* __restrict__ A,
                                     signed char* __restrict__ Ph, signed char* __restrict__ Pl,
                                     float* __restrict__ sP)
{
    __shared__ float sh[4];
    int row = blockIdx.x;
    const float* a = A + (size_t)row * NS;
    int tid = threadIdx.x;

    float v0 = a[tid], v1 = a[tid + 128], v2 = a[tid + 256], v3 = a[tid + 384];
    float mx = fmaxf(fmaxf(v0, v1), fmaxf(v2, v3));
#pragma unroll
    for (int o = 16; o > 0; o >>= 1) mx = fmaxf(mx, __shfl_xor_sync(0xffffffffu, mx, o));
    if ((tid & 31) == 0) sh[tid >> 5] = mx;
    __syncthreads();
    mx = fmaxf(fmaxf(sh[0], sh[1]), fmaxf(sh[2], sh[3]));
    __syncthreads();

    v0 = expf(v0 - mx); v1 = expf(v1 - mx); v2 = expf(v2 - mx); v3 = expf(v3 - mx);
    float s = v0 + v1 + v2 + v3;
#pragma unroll
    for (int o = 16; o > 0; o >>= 1) s += __shfl_xor_sync(0xffffffffu, s, o);
    if ((tid & 31) == 0) sh[tid >> 5] = s;
    __syncthreads();
    s = sh[0] + sh[1] + sh[2] + sh[3];

    float inv = 1.0f / s;
    if (tid == 0) sP[row] = inv * (1.0f / 127.0f);
    size_t base = (size_t)row * NS;
    // P = v*inv ; P/sP = 127*v  (v <= 1)
#pragma unroll
    for (int j = 0; j < 4; j++) {
        float v = (j == 0) ? v0 : (j == 1) ? v1 : (j == 2) ? v2 : v3;
        float y = 127.0f * v;
        int hi = __float2int_rn(y); hi = max(-127, min(127, hi));
        int lo = __float2int_rn((y - (float)hi) * 256.0f); lo = max(-127, min(127, lo));
        Ph[base + tid + j * 128] = (signed char)hi;
        Pl[base + tid + j * 128] = (signed char)lo;
    }
}

// ---------------------------------------------------------------------------
// Mask fill + residual + LayerNorm (verified since R2)
// ---------------------------------------------------------------------------
__global__ void epilogue_kernel(const float* __restrict__ sem, const float* __restrict__ ocr,
                                const int* __restrict__ mask,
                                const float* __restrict__ lnw, const float* __restrict__ lnb,
                                float* __restrict__ out)
{
    __shared__ float sh[4];
    int row = blockIdx.x;
    int tid = threadIdx.x;
    float* y = out + (size_t)row * DS;

    if (mask[row] == 0) {
        for (int i = tid; i < DS; i += 128)
            y[i] = MASKED_CNORM * lnw[i] + lnb[i];
        return;
    }

    const float* o = ocr + (size_t)row * DS;
    const float* s = sem + (size_t)row * DS;

    float x0 = o[tid]       + s[tid];
    float x1 = o[tid + 128] + s[tid + 128];
    float x2 = 0.f;
    float sum = x0 + x1;
    if (tid < 44) { x2 = o[tid + 256] + s[tid + 256]; sum += x2; }

#pragma unroll
    for (int oo = 16; oo > 0; oo >>= 1) sum += __shfl_xor_sync(0xffffffffu, sum, oo);
    if ((tid & 31) == 0) sh[tid >> 5] = sum;
    __syncthreads();
    sum = sh[0] + sh[1] + sh[2] + sh[3];
    __syncthreads();

    float mu = sum * (1.0f / 300.0f);
    float d0 = x0 - mu, d1 = x1 - mu, d2 = (tid < 44) ? (x2 - mu) : 0.f;
    float vs = d0 * d0 + d1 * d1 + d2 * d2;
#pragma unroll
    for (int oo = 16; oo > 0; oo >>= 1) vs += __shfl_xor_sync(0xffffffffu, vs, oo);
    if ((tid & 31) == 0) sh[tid >> 5] = vs;
    __syncthreads();
    vs = sh[0] + sh[1] + sh[2] + sh[3];

    float inv = rsqrtf(vs * (1.0f / 300.0f) + 1e-5f);
    y[tid]       = d0 * inv * lnw[tid]       + lnb[tid];
    y[tid + 128] = d1 * inv * lnw[tid + 128] + lnb[tid + 128];
    if (tid < 44)
        y[tid + 256] = d2 * inv * lnw[tid + 256] + lnb[tid + 256];
}

// ---------------------------------------------------------------------------
extern "C" void kernel_launch(void* const* d_in, const int* in_sizes, int n_in,
                              void* d_out, int out_size)
{
    const float* concepts = (const float*)d_in[0];
    const float* ocr      = (const float*)d_in[1];
    const int*   mask     = (const int*)d_in[2];
    const float* wq       = (const float*)d_in[3];
    const float* bq       = (const float*)d_in[4];
    const float* wk       = (const float*)d_in[5];
    const float* bk       = (const float*)d_in[6];
    const float* lnw      = (const float*)d_in[7];
    const float* lnb      = (const float*)d_in[8];
    float* out = (float*)d_out;

    cudaFuncSetAttribute(gemm_s8_kernel, cudaFuncAttributeMaxDynamicSharedMemorySize, GEMM_SMEM);

    signed char *c8h,*c8l,*o8h,*o8l,*ct8h,*ct8l,*wq8h,*wq8l,*wk8h,*wk8l,*q8h,*q8l,*k8h,*k8l,*p8h,*p8l;
    float *A,*T,*U,*S,*sC,*sO,*sWq,*sWk,*sQ,*sK,*sP,*sCt;
    cudaGetSymbolAddress((void**)&c8h, g_c8h);   cudaGetSymbolAddress((void**)&c8l, g_c8l);
    cudaGetSymbolAddress((void**)&o8h, g_o8h);   cudaGetSymbolAddress((void**)&o8l, g_o8l);
    cudaGetSymbolAddress((void**)&ct8h, g_ct8h); cudaGetSymbolAddress((void**)&ct8l, g_ct8l);
    cudaGetSymbolAddress((void**)&wq8h, g_wq8h); cudaGetSymbolAddress((void**)&wq8l, g_wq8l);
    cudaGetSymbolAddress((void**)&wk8h, g_wk8h); cudaGetSymbolAddress((void**)&wk8l, g_wk8l);
    cudaGetSymbolAddress((void**)&q8h, g_q8h);   cudaGetSymbolAddress((void**)&q8l, g_q8l);
    cudaGetSymbolAddress((void**)&k8h, g_k8h);   cudaGetSymbolAddress((void**)&k8l, g_k8l);
    cudaGetSymbolAddress((void**)&p8h, g_p8h);   cudaGetSymbolAddress((void**)&p8l, g_p8l);
    cudaGetSymbolAddress((void**)&A, g_A);       cudaGetSymbolAddress((void**)&T, g_T);
    cudaGetSymbolAddress((void**)&U, g_U);       cudaGetSymbolAddress((void**)&S, g_S);
    cudaGetSymbolAddress((void**)&sC, g_sC);     cudaGetSymbolAddress((void**)&sO, g_sO);
    cudaGetSymbolAddress((void**)&sWq, g_sWq);   cudaGetSymbolAddress((void**)&sWk, g_sWk);
    cudaGetSymbolAddress((void**)&sQ, g_sQ);     cudaGetSymbolAddress((void**)&sK, g_sK);
    cudaGetSymbolAddress((void**)&sP, g_sP);     cudaGetSymbolAddress((void**)&sCt, g_sCt);

    // Quantize inputs (per-row 2-limb s8)
    quant_rows_kernel<<<BN_ROWS, 128>>>(concepts, DS, DS, DP, c8h, c8l, sC);
    quant_rows_kernel<<<BN_ROWS, 128>>>(ocr,      DS, DS, DP, o8h, o8l, sO);
    quant_rows_kernel<<<DS, 128>>>(wq, DS, DS, DP, wq8h, wq8l, sWq);
    quant_rows_kernel<<<DS, 128>>>(wk, DS, DS, DP, wk8h, wk8l, sWk);
    // concepts^T fp32 (staged in g_A, overwritten by scores later), then quantize
    {
        dim3 tg((DS + 31) / 32, NS / 32, BB);
        transpose_kernel<<<tg, dim3(32, 8)>>>(concepts, A);
        quant_rows_kernel<<<BB * DS, 128>>>(A, NS, NS, NS, ct8h, ct8l, sCt);
    }

    // Q = concepts @ wq^T + bq (fp32), K = ocr @ wk^T + bk
    gemm_s8_kernel<<<dim3(BN_ROWS/128, 3, 1), 256, GEMM_SMEM>>>(
        c8h, c8l, wq8h, wq8l, sC, sWq, bq, T,
        BN_ROWS, DS, DP, DS, 0, 0, 0, 0, 0, 1.0f);
    gemm_s8_kernel<<<dim3(BN_ROWS/128, 3, 1), 256, GEMM_SMEM>>>(
        o8h, o8l, wk8h, wk8l, sO, sWk, bk, U,
        BN_ROWS, DS, DP, DS, 0, 0, 0, 0, 0, 1.0f);

    // Quantize Q, K per row
    quant_rows_kernel<<<BN_ROWS, 128>>>(T, DS, DS, DP, q8h, q8l, sQ);
    quant_rows_kernel<<<BN_ROWS, 128>>>(U, DS, DS, DP, k8h, k8l, sK);

    // scores[b] = (Q K^T)/sqrt(D)  -> g_A
    gemm_s8_kernel<<<dim3(NS/128, NS/128, BB), 256, GEMM_SMEM>>>(
        q8h, q8l, k8h, k8l, sQ, sK, nullptr, A,
        NS, NS, DP, NS,
        (long long)NS * DP, (long long)NS * DP, (long long)NS * NS,
        NS, NS, INV_SQRT_D);

    // softmax + quantize P
    softmax_quant_kernel<<<BN_ROWS, 128>>>(A, p8h, p8l, sP);

    // semantic[b] = P concepts[b]  (B = ct, NT)
    gemm_s8_kernel<<<dim3(NS/128, 3, BB), 256, GEMM_SMEM>>>(
        p8h, p8l, ct8h, ct8l, sP, sCt, nullptr, S,
        NS, DS, NS, DS,
        (long long)NS * NS, (long long)DS * NS, (long long)NS * DS,
        NS, DS, 1.0f);

    // mask + residual + LayerNorm
    epilogue_kernel<<<BN_ROWS, 128>>>(S, ocr, mask, lnw, lnb, out);

    (void)in_sizes; (void)n_in; (void)out_size;
}

// round 9
// speedup vs baseline: 1.9972x; 1.9972x over previous
#include <cuda_runtime.h>
#include <cuda_bf16.h>
#include <cstdint>

#define BB 64
#define NS 512
#define DS 300
#define DP 320                          // K padded to multiple of 32
#define BN_ROWS (BB*NS)                 // 32768
#define INV_SQRT_D 0.057735026918962576f
#define MASKED_CNORM (1.0f)

// ---------------------------------------------------------------------------
// Device-global scratch (runtime allocation forbidden); 16B-aligned rows.
// ---------------------------------------------------------------------------
__device__ alignas(1024) __nv_bfloat16 g_cbf_h[(size_t)BN_ROWS * DP];
__device__ alignas(1024) __nv_bfloat16 g_cbf_l[(size_t)BN_ROWS * DP];
__device__ alignas(1024) __nv_bfloat16 g_obf_h[(size_t)BN_ROWS * DP];
__device__ alignas(1024) __nv_bfloat16 g_obf_l[(size_t)BN_ROWS * DP];
__device__ alignas(1024) __nv_bfloat16 g_ct_h[(size_t)BB * DS * NS];   // concepts^T [b][d][m]
__device__ alignas(1024) __nv_bfloat16 g_ct_l[(size_t)BB * DS * NS];
__device__ alignas(1024) __nv_bfloat16 g_wq_h[DS * DP];
__device__ alignas(1024) __nv_bfloat16 g_wq_l[DS * DP];
__device__ alignas(1024) __nv_bfloat16 g_wk_h[DS * DP];
__device__ alignas(1024) __nv_bfloat16 g_wk_l[DS * DP];
__device__ alignas(1024) __nv_bfloat16 g_Qh[(size_t)BN_ROWS * DP];
__device__ alignas(1024) __nv_bfloat16 g_Ql[(size_t)BN_ROWS * DP];
__device__ alignas(1024) __nv_bfloat16 g_Kh[(size_t)BN_ROWS * DP];
__device__ alignas(1024) __nv_bfloat16 g_Kl[(size_t)BN_ROWS * DP];
__device__ alignas(1024) float         g_A[(size_t)BB * NS * NS];      // scores fp32
__device__ alignas(1024) __nv_bfloat16 g_Ph[(size_t)BB * NS * NS];
__device__ alignas(1024) __nv_bfloat16 g_Pl[(size_t)BB * NS * NS];
__device__ alignas(1024) float         g_S[(size_t)BN_ROWS * DS];      // semantic fp32

// ---------------------------------------------------------------------------
// PTX helpers (sm_80-era only; compiles under compute_103)
// ---------------------------------------------------------------------------
__device__ __forceinline__ uint32_t smem_to_u32(const void* p) {
    uint32_t a;
    asm("{ .reg .u64 t; cvta.to.shared.u64 t, %1; cvt.u32.u64 %0, t; }" : "=r"(a) : "l"(p));
    return a;
}
__device__ __forceinline__ void cp_async16(uint32_t dst, const void* src) {
    asm volatile("cp.async.cg.shared.global [%0], [%1], 16;"
                 :: "r"(dst), "l"(src) : "memory");
}
#define CP_COMMIT() asm volatile("cp.async.commit_group;" ::: "memory")
#define CP_WAIT(n)  asm volatile("cp.async.wait_group %0;" :: "n"(n) : "memory")

__device__ __forceinline__ void ldsm_x4(uint32_t* r, uint32_t addr) {
    asm volatile("ldmatrix.sync.aligned.m8n8.x4.shared.b16 {%0,%1,%2,%3}, [%4];"
                 : "=r"(r[0]), "=r"(r[1]), "=r"(r[2]), "=r"(r[3]) : "r"(addr));
}
__device__ __forceinline__ void mma16816(float* d, const uint32_t* a, const uint32_t* b) {
    asm volatile("mma.sync.aligned.m16n8k16.row.col.f32.bf16.bf16.f32 "
                 "{%0,%1,%2,%3}, {%4,%5,%6,%7}, {%8,%9}, {%0,%1,%2,%3};"
                 : "+f"(d[0]), "+f"(d[1]), "+f"(d[2]), "+f"(d[3])
                 : "r"(a[0]), "r"(a[1]), "r"(a[2]), "r"(a[3]), "r"(b[0]), "r"(b[1]));
}

__device__ __forceinline__ void bf16_split(float x, __nv_bfloat16& h, __nv_bfloat16& l) {
    h = __float2bfloat16(x);
    l = __float2bfloat16(x - __bfloat162float(h));
}

// ---------------------------------------------------------------------------
// GEMM (NT): C[r,c] = scale * sum_k A[r,k]*B[c,k] (+bias[c]), bf16 hi/lo 3-pass.
// CTA tile 256(M) x 128(N), BK=32, 256 threads, 8 warps (4m x 2n), warp 64x64.
// 3-stage cp.async pipeline; OOB B rows skip their cp.async entirely (garbage
// columns never read in epilogue). REQUIRES K%32==0, M%256==0, 16B alignment.
// ---------------------------------------------------------------------------
#define ROW_B   80                     // 64B data + 16B pad (ldsm conflict-free)
#define A_TILE  (256 * ROW_B)          // 20480
#define B_TILE  (128 * ROW_B)          // 10240
#define OFF_AH  0
#define OFF_AL  (1 * A_TILE)
#define OFF_BH  (2 * A_TILE)
#define OFF_BL  (2 * A_TILE + B_TILE)
#define STAGE_B (2 * A_TILE + 2 * B_TILE)   // 61440
#define NSTAGE  3
#define GEMM_SMEM (NSTAGE * STAGE_B)        // 184320

__global__ void __launch_bounds__(256)
gemm_mma_kernel(const __nv_bfloat16* __restrict__ Ah, const __nv_bfloat16* __restrict__ Al,
                const __nv_bfloat16* __restrict__ Bh, const __nv_bfloat16* __restrict__ Bl,
                const float* __restrict__ bias,
                float* __restrict__ Cf, __nv_bfloat16* __restrict__ Ch, __nv_bfloat16* __restrict__ Cl,
                int M, int N, int K, int ldc,
                long long sA, long long sB, long long sC, float scale)
{
    extern __shared__ __align__(128) char smem[];
    uint32_t smem_base = smem_to_u32(smem);
    int tid = threadIdx.x;
    int wid = tid >> 5, lane = tid & 31;
    int wm = wid >> 1, wn = wid & 1;          // 4m x 2n
    int z = blockIdx.z;
    int rowBase = blockIdx.x * 256;
    int colBase = blockIdx.y * 128;

    const __nv_bfloat16* pAh = Ah + (size_t)z * sA;
    const __nv_bfloat16* pAl = Al + (size_t)z * sA;
    const __nv_bfloat16* pBh = Bh + (size_t)z * sB;
    const __nv_bfloat16* pBl = Bl + (size_t)z * sB;

    int nChunks = K >> 5;

    // 3072 16B-segments per chunk: A 2048 (2 limbs x 256 rows x 4), B 1024.
    auto prefetch = [&](int c, int stage) {
        int k0 = c << 5;
        uint32_t sb = smem_base + stage * STAGE_B;
#pragma unroll
        for (int i = 0; i < 12; i++) {
            int s = tid + i * 256;
            if (s < 2048) {
                int limb = s >> 10, r = (s >> 2) & 255, cs = s & 3;
                uint32_t d = sb + (limb ? OFF_AL : OFF_AH) + r * ROW_B + cs * 16;
                const __nv_bfloat16* src = (limb ? pAl : pAh) +
                    (size_t)(rowBase + r) * K + k0 + cs * 8;
                cp_async16(d, src);
            } else {
                int t = s - 2048;
                int limb = t >> 9, r = (t >> 2) & 127, cs = t & 3;
                int bRow = colBase + r;
                if (bRow < N) {                       // skip OOB rows entirely
                    uint32_t d = sb + (limb ? OFF_BL : OFF_BH) + r * ROW_B + cs * 16;
                    const __nv_bfloat16* src = (limb ? pBl : pBh) +
                        (size_t)bRow * K + k0 + cs * 8;
                    cp_async16(d, src);
                }
            }
        }
    };

    float acc[4][8][4];
#pragma unroll
    for (int mi = 0; mi < 4; mi++)
#pragma unroll
        for (int ni = 0; ni < 8; ni++)
#pragma unroll
            for (int j = 0; j < 4; j++) acc[mi][ni][j] = 0.f;

    prefetch(0, 0); CP_COMMIT();
    if (nChunks > 1) prefetch(1, 1);
    CP_COMMIT();

#pragma unroll 1
    for (int c = 0; c < nChunks; c++) {
        int st = c % 3;
        if (c + 2 < nChunks) prefetch(c + 2, (c + 2) % 3);
        CP_COMMIT();
        CP_WAIT(2);                       // chunk c's group complete
        __syncthreads();

        uint32_t sb = smem_base + st * STAGE_B;
#pragma unroll
        for (int ks = 0; ks < 2; ks++) {
            int kb = ks * 32;
            uint32_t ah[4][4], al[4][4], bcur[8][2];
#pragma unroll
            for (int mi = 0; mi < 4; mi++) {
                uint32_t addr = sb + OFF_AH +
                    (uint32_t)((wm * 64 + mi * 16 + (lane & 15)) * ROW_B + ((lane >> 4) * 16) + kb);
                ldsm_x4(ah[mi], addr);
                ldsm_x4(al[mi], addr + (OFF_AL - OFF_AH));
            }
            // b_hi: passes hh then lh (reuse), then b_lo: pass hl
#pragma unroll
            for (int g = 0; g < 4; g++) {
                int j = lane & 7, grp = lane >> 3;
                uint32_t addr = sb + OFF_BH +
                    (uint32_t)((wn * 64 + g * 16 + ((grp >> 1) * 8) + j) * ROW_B + ((grp & 1) * 16) + kb);
                uint32_t r[4];
                ldsm_x4(r, addr);
                bcur[2*g][0] = r[0]; bcur[2*g][1] = r[1];
                bcur[2*g+1][0] = r[2]; bcur[2*g+1][1] = r[3];
            }
#pragma unroll
            for (int mi = 0; mi < 4; mi++)
#pragma unroll
                for (int ni = 0; ni < 8; ni++)
                    mma16816(acc[mi][ni], ah[mi], bcur[ni]);   // hh
#pragma unroll
            for (int mi = 0; mi < 4; mi++)
#pragma unroll
                for (int ni = 0; ni < 8; ni++)
                    mma16816(acc[mi][ni], al[mi], bcur[ni]);   // lh
#pragma unroll
            for (int g = 0; g < 4; g++) {
                int j = lane & 7, grp = lane >> 3;
                uint32_t addr = sb + OFF_BL +
                    (uint32_t)((wn * 64 + g * 16 + ((grp >> 1) * 8) + j) * ROW_B + ((grp & 1) * 16) + kb);
                uint32_t r[4];
                ldsm_x4(r, addr);
                bcur[2*g][0] = r[0]; bcur[2*g][1] = r[1];
                bcur[2*g+1][0] = r[2]; bcur[2*g+1][1] = r[3];
            }
#pragma unroll
            for (int mi = 0; mi < 4; mi++)
#pragma unroll
                for (int ni = 0; ni < 8; ni++)
                    mma16816(acc[mi][ni], ah[mi], bcur[ni]);   // hl
        }
        __syncthreads();
    }

    // Epilogue (+ zero-fill of bf16 pad columns [N, ldc))
    float* Cfp = Cf ? Cf + (size_t)z * sC : nullptr;
    __nv_bfloat16* Chp = Ch ? Ch + (size_t)z * sC : nullptr;
    __nv_bfloat16* Clp = Cl ? Cl + (size_t)z * sC : nullptr;
#pragma unroll
    for (int mi = 0; mi < 4; mi++) {
#pragma unroll
        for (int ni = 0; ni < 8; ni++) {
#pragma unroll
            for (int half = 0; half < 2; half++) {
                int gm = rowBase + wm * 64 + mi * 16 + (lane >> 2) + half * 8;
                int gn = colBase + wn * 64 + ni * 8 + 2 * (lane & 3);
                size_t o = (size_t)gm * ldc + gn;
                if (gn < N) {
                    float v0 = acc[mi][ni][2*half]   * scale;
                    float v1 = acc[mi][ni][2*half+1] * scale;
                    if (bias) { v0 += bias[gn]; v1 += (gn + 1 < N) ? bias[gn+1] : 0.f; }
                    bool ok1 = (gn + 1 < N);
                    if (Cfp) {
                        Cfp[o] = v0;
                        if (ok1) Cfp[o+1] = v1;
                    }
                    if (Chp) {
                        __nv_bfloat16 hh, ll;
                        bf16_split(v0, hh, ll); Chp[o] = hh; Clp[o] = ll;
                        if (ok1) { bf16_split(v1, hh, ll); Chp[o+1] = hh; Clp[o+1] = ll; }
                        else if (gn + 1 < ldc) {
                            Chp[o+1] = __float2bfloat16(0.f); Clp[o+1] = __float2bfloat16(0.f);
                        }
                    }
                } else if (Chp && gn < ldc) {
                    __nv_bfloat16 zz = __float2bfloat16(0.f);
                    Chp[o] = zz; Clp[o] = zz;
                    if (gn + 1 < ldc) { Chp[o+1] = zz; Clp[o+1] = zz; }
                }
            }
        }
    }
}

// ---------------------------------------------------------------------------
// fp32 [rows x kin] -> bf16 hi/lo [rows x kout], zero pad cols [kin, kout).
// ---------------------------------------------------------------------------
__global__ void split_pad_kernel(const float* __restrict__ x, __nv_bfloat16* __restrict__ h,
                                 __nv_bfloat16* __restrict__ l, int rows, int kin, int kout)
{
    int q = kout >> 2;
    int i4 = blockIdx.x * blockDim.x + threadIdx.x;
    if (i4 >= rows * q) return;
    int r = i4 / q, c = (i4 - r * q) << 2;
    __nv_bfloat16 hv[4], lv[4];
    if (c < kin) {
        float4 v = *(const float4*)(x + (size_t)r * kin + c);
        bf16_split(v.x, hv[0], lv[0]);
        bf16_split(v.y, hv[1], lv[1]);
        bf16_split(v.z, hv[2], lv[2]);
        bf16_split(v.w, hv[3], lv[3]);
    } else {
        __nv_bfloat16 zz = __float2bfloat16(0.f);
        hv[0]=hv[1]=hv[2]=hv[3]=zz; lv[0]=lv[1]=lv[2]=lv[3]=zz;
    }
    size_t o = (size_t)r * kout + c;
    h[o]=hv[0]; h[o+1]=hv[1]; h[o+2]=hv[2]; h[o+3]=hv[3];
    l[o]=lv[0]; l[o+1]=lv[1]; l[o+2]=lv[2]; l[o+3]=lv[3];
}

// concepts [b][m][300] -> ct [b][d][512] with bf16 split
__global__ void transpose_split_kernel(const float* __restrict__ in,
                                       __nv_bfloat16* __restrict__ oh,
                                       __nv_bfloat16* __restrict__ ol)
{
    __shared__ float t[32][33];
    int b = blockIdx.z;
    int dBase = blockIdx.x * 32, mBase = blockIdx.y * 32;
    int tx = threadIdx.x, ty = threadIdx.y;
#pragma unroll
    for (int i = 0; i < 4; i++) {
        int m = mBase + ty + i * 8, d = dBase + tx;
        if (d < DS) t[ty + i * 8][tx] = in[((size_t)b * NS + m) * DS + d];
    }
    __syncthreads();
#pragma unroll
    for (int i = 0; i < 4; i++) {
        int d = dBase + ty + i * 8, m = mBase + tx;
        if (d < DS) {
            __nv_bfloat16 hh, ll;
            bf16_split(t[tx][ty + i * 8], hh, ll);
            size_t o = ((size_t)b * DS + d) * NS + m;
            oh[o] = hh; ol[o] = ll;
        }
    }
}

// ---------------------------------------------------------------------------
// Row softmax over N=512, output bf16 hi/lo split of probs
// ---------------------------------------------------------------------------
__global__ void softmax_split_kernel(const float* __restrict__ A,
                                     __nv_bfloat16* __restrict__ Ph,
                                     __nv_bfloat16* __restrict__ Pl)
{
    __shared__ float sh[4];
    int row = blockIdx.x;
    const float* a = A + (size_t)row * NS;
    int tid = threadIdx.x;

    float v0 = a[tid], v1 = a[tid + 128], v2 = a[tid + 256], v3 = a[tid + 384];
    float mx = fmaxf(fmaxf(v0, v1), fmaxf(v2, v3));
#pragma unroll
    for (int o = 16; o > 0; o >>= 1) mx = fmaxf(mx, __shfl_xor_sync(0xffffffffu, mx, o));
    if ((tid & 31) == 0) sh[tid >> 5] = mx;
    __syncthreads();
    mx = fmaxf(fmaxf(sh[0], sh[1]), fmaxf(sh[2], sh[3]));
    __syncthreads();

    v0 = expf(v0 - mx); v1 = expf(v1 - mx); v2 = expf(v2 - mx); v3 = expf(v3 - mx);
    float s = v0 + v1 + v2 + v3;
#pragma unroll
    for (int o = 16; o > 0; o >>= 1) s += __shfl_xor_sync(0xffffffffu, s, o);
    if ((tid & 31) == 0) sh[tid >> 5] = s;
    __syncthreads();
    s = sh[0] + sh[1] + sh[2] + sh[3];

    float inv = 1.0f / s;
    __nv_bfloat16 hh, ll;
    size_t base = (size_t)row * NS;
    bf16_split(v0 * inv, hh, ll); Ph[base + tid]       = hh; Pl[base + tid]       = ll;
    bf16_split(v1 * inv, hh, ll); Ph[base + tid + 128] = hh; Pl[base + tid + 128] = ll;
    bf16_split(v2 * inv, hh, ll); Ph[base + tid + 256] = hh; Pl[base + tid + 256] = ll;
    bf16_split(v3 * inv, hh, ll); Ph[base + tid + 384] = hh; Pl[base + tid + 384] = ll;
}

// ---------------------------------------------------------------------------
// Mask fill + residual + LayerNorm (verified since R2)
// ---------------------------------------------------------------------------
__global__ void epilogue_kernel(const float* __restrict__ sem, const float* __restrict__ ocr,
                                const int* __restrict__ mask,
                                const float* __restrict__ lnw, const float* __restrict__ lnb,
                                float* __restrict__ out)
{
    __shared__ float sh[4];
    int row = blockIdx.x;
    int tid = threadIdx.x;
    float* y = out + (size_t)row * DS;

    if (mask[row] == 0) {
        for (int i = tid; i < DS; i += 128)
            y[i] = MASKED_CNORM * lnw[i] + lnb[i];
        return;
    }

    const float* o = ocr + (size_t)row * DS;
    const float* s = sem + (size_t)row * DS;

    float x0 = o[tid]       + s[tid];
    float x1 = o[tid + 128] + s[tid + 128];
    float x2 = 0.f;
    float sum = x0 + x1;
    if (tid < 44) { x2 = o[tid + 256] + s[tid + 256]; sum += x2; }

#pragma unroll
    for (int oo = 16; oo > 0; oo >>= 1) sum += __shfl_xor_sync(0xffffffffu, sum, oo);
    if ((tid & 31) == 0) sh[tid >> 5] = sum;
    __syncthreads();
    sum = sh[0] + sh[1] + sh[2] + sh[3];
    __syncthreads();

    float mu = sum * (1.0f / 300.0f);
    float d0 = x0 - mu, d1 = x1 - mu, d2 = (tid < 44) ? (x2 - mu) : 0.f;
    float vs = d0 * d0 + d1 * d1 + d2 * d2;
#pragma unroll
    for (int oo = 16; oo > 0; oo >>= 1) vs += __shfl_xor_sync(0xffffffffu, vs, oo);
    if ((tid & 31) == 0) sh[tid >> 5] = vs;
    __syncthreads();
    vs = sh[0] + sh[1] + sh[2] + sh[3];

    float inv = rsqrtf(vs * (1.0f / 300.0f) + 1e-5f);
    y[tid]       = d0 * inv * lnw[tid]       + lnb[tid];
    y[tid + 128] = d1 * inv * lnw[tid + 128] + lnb[tid + 128];
    if (tid < 44)
        y[tid + 256] = d2 * inv * lnw[tid + 256] + lnb[tid + 256];
}

// ---------------------------------------------------------------------------
extern "C" void kernel_launch(void* const* d_in, const int* in_sizes, int n_in,
                              void* d_out, int out_size)
{
    const float* concepts = (const float*)d_in[0];
    const float* ocr      = (const float*)d_in[1];
    const int*   mask     = (const int*)d_in[2];
    const float* wq       = (const float*)d_in[3];
    const float* bq       = (const float*)d_in[4];
    const float* wk       = (const float*)d_in[5];
    const float* bk       = (const float*)d_in[6];
    const float* lnw      = (const float*)d_in[7];
    const float* lnb      = (const float*)d_in[8];
    float* out = (float*)d_out;

    cudaFuncSetAttribute(gemm_mma_kernel, cudaFuncAttributeMaxDynamicSharedMemorySize, GEMM_SMEM);

    __nv_bfloat16 *cbf_h, *cbf_l, *obf_h, *obf_l, *ct_h, *ct_l;
    __nv_bfloat16 *wqh, *wql, *wkh, *wkl, *Qh, *Ql, *Kh, *Kl, *Ph, *Pl;
    float *A, *S;
    cudaGetSymbolAddress((void**)&cbf_h, g_cbf_h); cudaGetSymbolAddress((void**)&cbf_l, g_cbf_l);
    cudaGetSymbolAddress((void**)&obf_h, g_obf_h); cudaGetSymbolAddress((void**)&obf_l, g_obf_l);
    cudaGetSymbolAddress((void**)&ct_h, g_ct_h);   cudaGetSymbolAddress((void**)&ct_l, g_ct_l);
    cudaGetSymbolAddress((void**)&wqh, g_wq_h);    cudaGetSymbolAddress((void**)&wql, g_wq_l);
    cudaGetSymbolAddress((void**)&wkh, g_wk_h);    cudaGetSymbolAddress((void**)&wkl, g_wk_l);
    cudaGetSymbolAddress((void**)&Qh, g_Qh);       cudaGetSymbolAddress((void**)&Ql, g_Ql);
    cudaGetSymbolAddress((void**)&Kh, g_Kh);       cudaGetSymbolAddress((void**)&Kl, g_Kl);
    cudaGetSymbolAddress((void**)&Ph, g_Ph);       cudaGetSymbolAddress((void**)&Pl, g_Pl);
    cudaGetSymbolAddress((void**)&A, g_A);         cudaGetSymbolAddress((void**)&S, g_S);

    // operand splits into padded [.. x 320] layouts (zeros in pad)
    {
        int t1 = BN_ROWS * (DP / 4);
        split_pad_kernel<<<(t1 + 255) / 256, 256>>>(concepts, cbf_h, cbf_l, BN_ROWS, DS, DP);
        split_pad_kernel<<<(t1 + 255) / 256, 256>>>(ocr,      obf_h, obf_l, BN_ROWS, DS, DP);
        int t2 = DS * (DP / 4);
        split_pad_kernel<<<(t2 + 255) / 256, 256>>>(wq, wqh, wql, DS, DS, DP);
        split_pad_kernel<<<(t2 + 255) / 256, 256>>>(wk, wkh, wkl, DS, DS, DP);
        dim3 tg((DS + 31) / 32, NS / 32, BB);
        transpose_split_kernel<<<tg, dim3(32, 8)>>>(concepts, ct_h, ct_l);
    }

    // Q = concepts @ wq^T + bq -> bf16 split (ldc=320)   [32768 x 300]
    gemm_mma_kernel<<<dim3(BN_ROWS / 256, 3, 1), 256, GEMM_SMEM>>>(
        cbf_h, cbf_l, wqh, wql, bq, nullptr, Qh, Ql,
        BN_ROWS, DS, DP, DP, 0, 0, 0, 1.0f);
    // K = ocr @ wk^T + bk -> bf16 split
    gemm_mma_kernel<<<dim3(BN_ROWS / 256, 3, 1), 256, GEMM_SMEM>>>(
        obf_h, obf_l, wkh, wkl, bk, nullptr, Kh, Kl,
        BN_ROWS, DS, DP, DP, 0, 0, 0, 1.0f);

    // A[b] = (Q[b] @ K[b]^T) / sqrt(D)   fp32
    gemm_mma_kernel<<<dim3(NS / 256, NS / 128, BB), 256, GEMM_SMEM>>>(
        Qh, Ql, Kh, Kl, nullptr, A, nullptr, nullptr,
        NS, NS, DP, NS,
        (long long)NS * DP, (long long)NS * DP, (long long)NS * NS, INV_SQRT_D);

    // softmax -> P bf16 split
    softmax_split_kernel<<<BN_ROWS, 128>>>(A, Ph, Pl);

    // sem[b] = P[b] @ concepts[b]  (B = concepts^T, NT form, K=512)   fp32
    gemm_mma_kernel<<<dim3(NS / 256, 3, BB), 256, GEMM_SMEM>>>(
        Ph, Pl, ct_h, ct_l, nullptr, S, nullptr, nullptr,
        NS, DS, NS, DS,
        (long long)NS * NS, (long long)DS * NS, (long long)NS * DS, 1.0f);

    // mask + residual + LayerNorm
    epilogue_kernel<<<BN_ROWS, 128>>>(S, ocr, mask, lnw, lnb, out);

    (void)in_sizes; (void)n_in; (void)out_size;
}

// round 10
// speedup vs baseline: 2.3489x; 1.1761x over previous
#include <cuda_runtime.h>
#include <cuda_fp16.h>
#include <cstdint>

#define BB 64
#define NS 512
#define DS 300
#define DP 320                          // K padded to multiple of 32
#define BN_ROWS (BB*NS)                 // 32768
#define INV_SQRT_D 0.057735026918962576f
#define MASKED_CNORM (1.0f)

// ---------------------------------------------------------------------------
// Device-global scratch (runtime allocation forbidden); 16B-aligned rows.
// A-role operands: 1 limb (hi). B-role operands: 2 limbs (hi+lo).
// ---------------------------------------------------------------------------
__device__ alignas(1024) __half g_c_h[(size_t)BN_ROWS * DP];     // concepts hi (A in proj-Q)
__device__ alignas(1024) __half g_o_h[(size_t)BN_ROWS * DP];     // ocr hi      (A in proj-K)
__device__ alignas(1024) __half g_ct_h[(size_t)BB * DS * NS];    // concepts^T hi (B in PV)
__device__ alignas(1024) __half g_ct_l[(size_t)BB * DS * NS];
__device__ alignas(1024) __half g_wq_h[DS * DP];                 // weights (B in proj)
__device__ alignas(1024) __half g_wq_l[DS * DP];
__device__ alignas(1024) __half g_wk_h[DS * DP];
__device__ alignas(1024) __half g_wk_l[DS * DP];
__device__ alignas(1024) __half g_Qh[(size_t)BN_ROWS * DP];      // Q hi (A in scores)
__device__ alignas(1024) __half g_Kh[(size_t)BN_ROWS * DP];      // K hi+lo (B in scores)
__device__ alignas(1024) __half g_Kl[(size_t)BN_ROWS * DP];
__device__ alignas(1024) __half g_Ph[(size_t)BB * NS * NS];      // P hi (A in PV)
__device__ alignas(1024) float  g_A[(size_t)BB * NS * NS];       // scores fp32
__device__ alignas(1024) float  g_S[(size_t)BN_ROWS * DS];       // semantic fp32

// ---------------------------------------------------------------------------
// PTX helpers (sm_80-era only; compiles under compute_103)
// ---------------------------------------------------------------------------
__device__ __forceinline__ uint32_t smem_to_u32(const void* p) {
    uint32_t a;
    asm("{ .reg .u64 t; cvta.to.shared.u64 t, %1; cvt.u32.u64 %0, t; }" : "=r"(a) : "l"(p));
    return a;
}
__device__ __forceinline__ void cp_async16(uint32_t dst, const void* src) {
    asm volatile("cp.async.cg.shared.global [%0], [%1], 16;"
                 :: "r"(dst), "l"(src) : "memory");
}
#define CP_COMMIT() asm volatile("cp.async.commit_group;" ::: "memory")
#define CP_WAIT(n)  asm volatile("cp.async.wait_group %0;" :: "n"(n) : "memory")

__device__ __forceinline__ void ldsm_x4(uint32_t* r, uint32_t addr) {
    asm volatile("ldmatrix.sync.aligned.m8n8.x4.shared.b16 {%0,%1,%2,%3}, [%4];"
                 : "=r"(r[0]), "=r"(r[1]), "=r"(r[2]), "=r"(r[3]) : "r"(addr));
}
__device__ __forceinline__ void mma16816h(float* d, const uint32_t* a, const uint32_t* b) {
    asm volatile("mma.sync.aligned.m16n8k16.row.col.f32.f16.f16.f32 "
                 "{%0,%1,%2,%3}, {%4,%5,%6,%7}, {%8,%9}, {%0,%1,%2,%3};"
                 : "+f"(d[0]), "+f"(d[1]), "+f"(d[2]), "+f"(d[3])
                 : "r"(a[0]), "r"(a[1]), "r"(a[2]), "r"(a[3]), "r"(b[0]), "r"(b[1]));
}

__device__ __forceinline__ void fp16_split(float x, __half& h, __half& l) {
    h = __float2half(x);
    l = __float2half(x - __half2float(h));
}

// ---------------------------------------------------------------------------
// GEMM (NT): C[r,c] = scale * sum_k A[r,k]*B[c,k] (+bias[c])
// fp16 2-pass: A 1-limb (hi), B 2-limb; passes a_h*b_h + a_h*b_l.
// CTA tile 256(M) x 128(N), BK=32, 256 threads, 8 warps (wm=wid&3, wn=wid>>2).
// Per-warp nCap trims MMA n-columns to the true N (N-exact).
// 3-stage cp.async pipeline; OOB B rows skip cp.async entirely.
// REQUIRES K%32==0, M%256==0, 16B alignment.
// ---------------------------------------------------------------------------
#define ROW_B   80                     // 64B data + 16B pad (ldsm conflict-free)
#define A_TILE  (256 * ROW_B)          // 20480
#define B_TILE  (128 * ROW_B)          // 10240
#define OFF_A   0
#define OFF_BH  (A_TILE)
#define OFF_BL  (A_TILE + B_TILE)
#define STAGE_B (A_TILE + 2 * B_TILE)  // 40960
#define NSTAGE  3
#define GEMM_SMEM (NSTAGE * STAGE_B)   // 122880

__global__ void __launch_bounds__(256)
gemm_mma_kernel(const __half* __restrict__ Ah,
                const __half* __restrict__ Bh, const __half* __restrict__ Bl,
                const float* __restrict__ bias,
                float* __restrict__ Cf, __half* __restrict__ Ch, __half* __restrict__ Cl,
                int M, int N, int K, int ldc,
                long long sA, long long sB, long long sC, float scale)
{
    extern __shared__ __align__(128) char smem[];
    uint32_t smem_base = smem_to_u32(smem);
    int tid = threadIdx.x;
    int wid = tid >> 5, lane = tid & 31;
    int wm = wid & 3, wn = wid >> 2;          // 4m x 2n, SMSP-balanced for trimming
    int z = blockIdx.z;
    int rowBase = blockIdx.x * 256;
    int colBase = blockIdx.y * 128;

    // N-exact cap: number of active ni columns (each 8 wide) for this warp
    int rem = N - colBase - wn * 64;
    int nCap = rem >= 64 ? 8 : (rem <= 0 ? 0 : ((rem + 7) >> 3));

    const __half* pAh = Ah + (size_t)z * sA;
    const __half* pBh = Bh + (size_t)z * sB;
    const __half* pBl = Bl + (size_t)z * sB;

    int nChunks = K >> 5;

    // 2048 16B-segments per chunk: A 1024 (256 rows x 4), B 1024 (2 limbs x 128 x 4)
    auto prefetch = [&](int c, int stage) {
        int k0 = c << 5;
        uint32_t sb = smem_base + stage * STAGE_B;
#pragma unroll
        for (int i = 0; i < 8; i++) {
            int s = tid + i * 256;
            if (s < 1024) {
                int r = s >> 2, cs = s & 3;
                cp_async16(sb + OFF_A + r * ROW_B + cs * 16,
                           pAh + (size_t)(rowBase + r) * K + k0 + cs * 8);
            } else {
                int t = s - 1024;
                int limb = t >> 9, r = (t >> 2) & 127, cs = t & 3;
                int bRow = colBase + r;
                if (bRow < N) {
                    cp_async16(sb + (limb ? OFF_BL : OFF_BH) + r * ROW_B + cs * 16,
                               (limb ? pBl : pBh) + (size_t)bRow * K + k0 + cs * 8);
                }
            }
        }
    };

    float acc[4][8][4];
#pragma unroll
    for (int mi = 0; mi < 4; mi++)
#pragma unroll
        for (int ni = 0; ni < 8; ni++)
#pragma unroll
            for (int j = 0; j < 4; j++) acc[mi][ni][j] = 0.f;

    prefetch(0, 0); CP_COMMIT();
    if (nChunks > 1) prefetch(1, 1);
    CP_COMMIT();

#pragma unroll 1
    for (int c = 0; c < nChunks; c++) {
        int st = c % 3;
        if (c + 2 < nChunks) prefetch(c + 2, (c + 2) % 3);
        CP_COMMIT();
        CP_WAIT(2);
        __syncthreads();

        uint32_t sb = smem_base + st * STAGE_B;
#pragma unroll
        for (int ks = 0; ks < 2; ks++) {
            int kb = ks * 32;
            uint32_t ah[4][4], bcur[8][2];
#pragma unroll
            for (int mi = 0; mi < 4; mi++) {
                uint32_t addr = sb + OFF_A +
                    (uint32_t)((wm * 64 + mi * 16 + (lane & 15)) * ROW_B + ((lane >> 4) * 16) + kb);
                ldsm_x4(ah[mi], addr);
            }
            // pass 1: a_h * b_h
#pragma unroll
            for (int g = 0; g < 4; g++) {
                if (g * 2 < nCap) {
                    int j = lane & 7, grp = lane >> 3;
                    uint32_t addr = sb + OFF_BH +
                        (uint32_t)((wn * 64 + g * 16 + ((grp >> 1) * 8) + j) * ROW_B
                                   + ((grp & 1) * 16) + kb);
                    uint32_t r[4];
                    ldsm_x4(r, addr);
                    bcur[2*g][0] = r[0]; bcur[2*g][1] = r[1];
                    bcur[2*g+1][0] = r[2]; bcur[2*g+1][1] = r[3];
                }
            }
#pragma unroll
            for (int mi = 0; mi < 4; mi++)
#pragma unroll
                for (int ni = 0; ni < 8; ni++)
                    if (ni < nCap) mma16816h(acc[mi][ni], ah[mi], bcur[ni]);
            // pass 2: a_h * b_l
#pragma unroll
            for (int g = 0; g < 4; g++) {
                if (g * 2 < nCap) {
                    int j = lane & 7, grp = lane >> 3;
                    uint32_t addr = sb + OFF_BL +
                        (uint32_t)((wn * 64 + g * 16 + ((grp >> 1) * 8) + j) * ROW_B
                                   + ((grp & 1) * 16) + kb);
                    uint32_t r[4];
                    ldsm_x4(r, addr);
                    bcur[2*g][0] = r[0]; bcur[2*g][1] = r[1];
                    bcur[2*g+1][0] = r[2]; bcur[2*g+1][1] = r[3];
                }
            }
#pragma unroll
            for (int mi = 0; mi < 4; mi++)
#pragma unroll
                for (int ni = 0; ni < 8; ni++)
                    if (ni < nCap) mma16816h(acc[mi][ni], ah[mi], bcur[ni]);
        }
        __syncthreads();
    }

    // Epilogue: fp32 out and/or fp16 hi(+lo) out; pad cols [N, ldc) zero-filled.
    float* Cfp = Cf ? Cf + (size_t)z * sC : nullptr;
    __half* Chp = Ch ? Ch + (size_t)z * sC : nullptr;
    __half* Clp = Cl ? Cl + (size_t)z * sC : nullptr;
#pragma unroll
    for (int mi = 0; mi < 4; mi++) {
#pragma unroll
        for (int ni = 0; ni < 8; ni++) {
#pragma unroll
            for (int half = 0; half < 2; half++) {
                int gm = rowBase + wm * 64 + mi * 16 + (lane >> 2) + half * 8;
                int gn = colBase + wn * 64 + ni * 8 + 2 * (lane & 3);
                if (gn >= ldc) continue;
                size_t o = (size_t)gm * ldc + gn;
                if (gn < N) {
                    float v0 = acc[mi][ni][2*half]   * scale;
                    float v1 = acc[mi][ni][2*half+1] * scale;
                    if (bias) { v0 += bias[gn]; v1 += (gn + 1 < N) ? bias[gn+1] : 0.f; }
                    bool ok1 = (gn + 1 < N);
                    if (Cfp) {
                        Cfp[o] = v0;
                        if (ok1) Cfp[o+1] = v1;
                    }
                    if (Chp) {
                        __half hh, ll;
                        fp16_split(v0, hh, ll);
                        Chp[o] = hh; if (Clp) Clp[o] = ll;
                        if (ok1) {
                            fp16_split(v1, hh, ll);
                            Chp[o+1] = hh; if (Clp) Clp[o+1] = ll;
                        } else if (gn + 1 < ldc) {
                            Chp[o+1] = __float2half(0.f);
                            if (Clp) Clp[o+1] = __float2half(0.f);
                        }
                    }
                } else if (Chp) {
                    __half zz = __float2half(0.f);
                    Chp[o] = zz; if (Clp) Clp[o] = zz;
                    if (gn + 1 < ldc) { Chp[o+1] = zz; if (Clp) Clp[o+1] = zz; }
                }
            }
        }
    }
}

// ---------------------------------------------------------------------------
// fp32 [rows x kin] -> fp16 hi (+ optional lo) [rows x kout], pad zero.
// ---------------------------------------------------------------------------
__global__ void split_pad_kernel(const float* __restrict__ x, __half* __restrict__ h,
                                 __half* __restrict__ l, int rows, int kin, int kout)
{
    int q = kout >> 2;
    int i4 = blockIdx.x * blockDim.x + threadIdx.x;
    if (i4 >= rows * q) return;
    int r = i4 / q, c = (i4 - r * q) << 2;
    __half hv[4], lv[4];
    if (c < kin) {
        float4 v = *(const float4*)(x + (size_t)r * kin + c);
        fp16_split(v.x, hv[0], lv[0]);
        fp16_split(v.y, hv[1], lv[1]);
        fp16_split(v.z, hv[2], lv[2]);
        fp16_split(v.w, hv[3], lv[3]);
    } else {
        __half zz = __float2half(0.f);
        hv[0]=hv[1]=hv[2]=hv[3]=zz; lv[0]=lv[1]=lv[2]=lv[3]=zz;
    }
    size_t o = (size_t)r * kout + c;
    h[o]=hv[0]; h[o+1]=hv[1]; h[o+2]=hv[2]; h[o+3]=hv[3];
    if (l) { l[o]=lv[0]; l[o+1]=lv[1]; l[o+2]=lv[2]; l[o+3]=lv[3]; }
}

// concepts [b][m][300] -> ct [b][d][512] fp16 2-limb
__global__ void transpose_split_kernel(const float* __restrict__ in,
                                       __half* __restrict__ oh, __half* __restrict__ ol)
{
    __shared__ float t[32][33];
    int b = blockIdx.z;
    int dBase = blockIdx.x * 32, mBase = blockIdx.y * 32;
    int tx = threadIdx.x, ty = threadIdx.y;
#pragma unroll
    for (int i = 0; i < 4; i++) {
        int m = mBase + ty + i * 8, d = dBase + tx;
        if (d < DS) t[ty + i * 8][tx] = in[((size_t)b * NS + m) * DS + d];
    }
    __syncthreads();
#pragma unroll
    for (int i = 0; i < 4; i++) {
        int d = dBase + ty + i * 8, m = mBase + tx;
        if (d < DS) {
            __half hh, ll;
            fp16_split(t[tx][ty + i * 8], hh, ll);
            size_t o = ((size_t)b * DS + d) * NS + m;
            oh[o] = hh; ol[o] = ll;
        }
    }
}

// ---------------------------------------------------------------------------
// Row softmax over N=512, output fp16 hi of probs
// ---------------------------------------------------------------------------
__global__ void softmax_h_kernel(const float* __restrict__ A, __half* __restrict__ Ph)
{
    __shared__ float sh[4];
    int row = blockIdx.x;
    const float* a = A + (size_t)row * NS;
    int tid = threadIdx.x;

    float v0 = a[tid], v1 = a[tid + 128], v2 = a[tid + 256], v3 = a[tid + 384];
    float mx = fmaxf(fmaxf(v0, v1), fmaxf(v2, v3));
#pragma unroll
    for (int o = 16; o > 0; o >>= 1) mx = fmaxf(mx, __shfl_xor_sync(0xffffffffu, mx, o));
    if ((tid & 31) == 0) sh[tid >> 5] = mx;
    __syncthreads();
    mx = fmaxf(fmaxf(sh[0], sh[1]), fmaxf(sh[2], sh[3]));
    __syncthreads();

    v0 = expf(v0 - mx); v1 = expf(v1 - mx); v2 = expf(v2 - mx); v3 = expf(v3 - mx);
    float s = v0 + v1 + v2 + v3;
#pragma unroll
    for (int o = 16; o > 0; o >>= 1) s += __shfl_xor_sync(0xffffffffu, s, o);
    if ((tid & 31) == 0) sh[tid >> 5] = s;
    __syncthreads();
    s = sh[0] + sh[1] + sh[2] + sh[3];

    float inv = 1.0f / s;
    size_t base = (size_t)row * NS;
    Ph[base + tid]       = __float2half(v0 * inv);
    Ph[base + tid + 128] = __float2half(v1 * inv);
    Ph[base + tid + 256] = __float2half(v2 * inv);
    Ph[base + tid + 384] = __float2half(v3 * inv);
}

// ---------------------------------------------------------------------------
// Mask fill + residual + LayerNorm (verified since R2)
// ---------------------------------------------------------------------------
__global__ void epilogue_kernel(const float* __restrict__ sem, const float* __restrict__ ocr,
                                const int* __restrict__ mask,
                                const float* __restrict__ lnw, const float* __restrict__ lnb,
                                float* __restrict__ out)
{
    __shared__ float sh[4];
    int row = blockIdx.x;
    int tid = threadIdx.x;
    float* y = out + (size_t)row * DS;

    if (mask[row] == 0) {
        for (int i = tid; i < DS; i += 128)
            y[i] = MASKED_CNORM * lnw[i] + lnb[i];
        return;
    }

    const float* o = ocr + (size_t)row * DS;
    const float* s = sem + (size_t)row * DS;

    float x0 = o[tid]       + s[tid];
    float x1 = o[tid + 128] + s[tid + 128];
    float x2 = 0.f;
    float sum = x0 + x1;
    if (tid < 44) { x2 = o[tid + 256] + s[tid + 256]; sum += x2; }

#pragma unroll
    for (int oo = 16; oo > 0; oo >>= 1) sum += __shfl_xor_sync(0xffffffffu, sum, oo);
    if ((tid & 31) == 0) sh[tid >> 5] = sum;
    __syncthreads();
    sum = sh[0] + sh[1] + sh[2] + sh[3];
    __syncthreads();

    float mu = sum * (1.0f / 300.0f);
    float d0 = x0 - mu, d1 = x1 - mu, d2 = (tid < 44) ? (x2 - mu) : 0.f;
    float vs = d0 * d0 + d1 * d1 + d2 * d2;
#pragma unroll
    for (int oo = 16; oo > 0; oo >>= 1) vs += __shfl_xor_sync(0xffffffffu, vs, oo);
    if ((tid & 31) == 0) sh[tid >> 5] = vs;
    __syncthreads();
    vs = sh[0] + sh[1] + sh[2] + sh[3];

    float inv = rsqrtf(vs * (1.0f / 300.0f) + 1e-5f);
    y[tid]       = d0 * inv * lnw[tid]       + lnb[tid];
    y[tid + 128] = d1 * inv * lnw[tid + 128] + lnb[tid + 128];
    if (tid < 44)
        y[tid + 256] = d2 * inv * lnw[tid + 256] + lnb[tid + 256];
}

// ---------------------------------------------------------------------------
extern "C" void kernel_launch(void* const* d_in, const int* in_sizes, int n_in,
                              void* d_out, int out_size)
{
    const float* concepts = (const float*)d_in[0];
    const float* ocr      = (const float*)d_in[1];
    const int*   mask     = (const int*)d_in[2];
    const float* wq       = (const float*)d_in[3];
    const float* bq       = (const float*)d_in[4];
    const float* wk       = (const float*)d_in[5];
    const float* bk       = (const float*)d_in[6];
    const float* lnw      = (const float*)d_in[7];
    const float* lnb      = (const float*)d_in[8];
    float* out = (float*)d_out;

    cudaFuncSetAttribute(gemm_mma_kernel, cudaFuncAttributeMaxDynamicSharedMemorySize, GEMM_SMEM);

    __half *c_h, *o_h, *ct_h, *ct_l, *wqh, *wql, *wkh, *wkl, *Qh, *Kh, *Kl, *Ph;
    float *A, *S;
    cudaGetSymbolAddress((void**)&c_h, g_c_h);
    cudaGetSymbolAddress((void**)&o_h, g_o_h);
    cudaGetSymbolAddress((void**)&ct_h, g_ct_h);  cudaGetSymbolAddress((void**)&ct_l, g_ct_l);
    cudaGetSymbolAddress((void**)&wqh, g_wq_h);   cudaGetSymbolAddress((void**)&wql, g_wq_l);
    cudaGetSymbolAddress((void**)&wkh, g_wk_h);   cudaGetSymbolAddress((void**)&wkl, g_wk_l);
    cudaGetSymbolAddress((void**)&Qh, g_Qh);
    cudaGetSymbolAddress((void**)&Kh, g_Kh);      cudaGetSymbolAddress((void**)&Kl, g_Kl);
    cudaGetSymbolAddress((void**)&Ph, g_Ph);
    cudaGetSymbolAddress((void**)&A, g_A);        cudaGetSymbolAddress((void**)&S, g_S);

    // operand splits (A-role: hi only; B-role: hi+lo), padded [.. x 320]
    {
        int t1 = BN_ROWS * (DP / 4);
        split_pad_kernel<<<(t1 + 255) / 256, 256>>>(concepts, c_h, nullptr, BN_ROWS, DS, DP);
        split_pad_kernel<<<(t1 + 255) / 256, 256>>>(ocr,      o_h, nullptr, BN_ROWS, DS, DP);
        int t2 = DS * (DP / 4);
        split_pad_kernel<<<(t2 + 255) / 256, 256>>>(wq, wqh, wql, DS, DS, DP);
        split_pad_kernel<<<(t2 + 255) / 256, 256>>>(wk, wkh, wkl, DS, DS, DP);
        dim3 tg((DS + 31) / 32, NS / 32, BB);
        transpose_split_kernel<<<tg, dim3(32, 8)>>>(concepts, ct_h, ct_l);
    }

    // Q = concepts @ wq^T + bq -> fp16 hi only (A-role downstream), ldc=320
    gemm_mma_kernel<<<dim3(BN_ROWS / 256, 3, 1), 256, GEMM_SMEM>>>(
        c_h, wqh, wql, bq, nullptr, Qh, nullptr,
        BN_ROWS, DS, DP, DP, 0, 0, 0, 1.0f);
    // K = ocr @ wk^T + bk -> fp16 hi+lo (B-role downstream)
    gemm_mma_kernel<<<dim3(BN_ROWS / 256, 3, 1), 256, GEMM_SMEM>>>(
        o_h, wkh, wkl, bk, nullptr, Kh, Kl,
        BN_ROWS, DS, DP, DP, 0, 0, 0, 1.0f);

    // scores[b] = (Q K^T)/sqrt(D)   fp32
    gemm_mma_kernel<<<dim3(NS / 256, NS / 128, BB), 256, GEMM_SMEM>>>(
        Qh, Kh, Kl, nullptr, A, nullptr, nullptr,
        NS, NS, DP, NS,
        (long long)NS * DP, (long long)NS * DP, (long long)NS * NS, INV_SQRT_D);

    // softmax -> P fp16 hi
    softmax_h_kernel<<<BN_ROWS, 128>>>(A, Ph);

    // sem[b] = P @ concepts[b]  (B = concepts^T 2-limb, NT, K=512)   fp32
    gemm_mma_kernel<<<dim3(NS / 256, 3, BB), 256, GEMM_SMEM>>>(
        Ph, ct_h, ct_l, nullptr, S, nullptr, nullptr,
        NS, DS, NS, DS,
        (long long)NS * NS, (long long)DS * NS, (long long)NS * DS, 1.0f);

    // mask + residual + LayerNorm
    epilogue_kernel<<<BN_ROWS, 128>>>(S, ocr, mask, lnw, lnb, out);

    (void)in_sizes; (void)n_in; (void)out_size;
}

// round 11
// speedup vs baseline: 2.6526x; 1.1293x over previous
#include <cuda_runtime.h>
#include <cuda_fp16.h>
#include <cstdint>

#define BB 64
#define NS 512
#define DS 300
#define DP 304                          // K padded to multiple of 16 (not 32)
#define BN_ROWS (BB*NS)                 // 32768
#define INV_SQRT_D 0.057735026918962576f
#define MASKED_CNORM (1.0f)

// ---------------------------------------------------------------------------
// Device-global scratch (runtime allocation forbidden); 16B-aligned rows
// (row strides 304*2=608B, 512*2=1024B — both %16==0).
// A-role operands: 1 limb. B-role: 2 limbs except PV's concepts^T (1 limb).
// ---------------------------------------------------------------------------
__device__ alignas(1024) __half g_c_h[(size_t)BN_ROWS * DP];     // concepts hi (A in proj-Q)
__device__ alignas(1024) __half g_o_h[(size_t)BN_ROWS * DP];     // ocr hi      (A in proj-K)
__device__ alignas(1024) __half g_ct_h[(size_t)BB * DS * NS];    // concepts^T hi (B in PV, 1-limb)
__device__ alignas(1024) __half g_wq_h[DS * DP];                 // weights (B in proj, 2-limb)
__device__ alignas(1024) __half g_wq_l[DS * DP];
__device__ alignas(1024) __half g_wk_h[DS * DP];
__device__ alignas(1024) __half g_wk_l[DS * DP];
__device__ alignas(1024) __half g_Qh[(size_t)BN_ROWS * DP];      // Q hi (A in scores)
__device__ alignas(1024) __half g_Kh[(size_t)BN_ROWS * DP];      // K hi+lo (B in scores)
__device__ alignas(1024) __half g_Kl[(size_t)BN_ROWS * DP];
__device__ alignas(1024) __half g_Ph[(size_t)BB * NS * NS];      // P hi (A in PV)
__device__ alignas(1024) float  g_A[(size_t)BB * NS * NS];       // scores fp32
__device__ alignas(1024) float  g_S[(size_t)BN_ROWS * DS];       // semantic fp32

// ---------------------------------------------------------------------------
// PTX helpers (sm_80-era only; compiles under compute_103)
// ---------------------------------------------------------------------------
__device__ __forceinline__ uint32_t smem_to_u32(const void* p) {
    uint32_t a;
    asm("{ .reg .u64 t; cvta.to.shared.u64 t, %1; cvt.u32.u64 %0, t; }" : "=r"(a) : "l"(p));
    return a;
}
__device__ __forceinline__ void cp_async16(uint32_t dst, const void* src) {
    asm volatile("cp.async.cg.shared.global [%0], [%1], 16;"
                 :: "r"(dst), "l"(src) : "memory");
}
#define CP_COMMIT() asm volatile("cp.async.commit_group;" ::: "memory")
#define CP_WAIT(n)  asm volatile("cp.async.wait_group %0;" :: "n"(n) : "memory")

__device__ __forceinline__ void ldsm_x4(uint32_t* r, uint32_t addr) {
    asm volatile("ldmatrix.sync.aligned.m8n8.x4.shared.b16 {%0,%1,%2,%3}, [%4];"
                 : "=r"(r[0]), "=r"(r[1]), "=r"(r[2]), "=r"(r[3]) : "r"(addr));
}
__device__ __forceinline__ void mma16816h(float* d, const uint32_t* a, const uint32_t* b) {
    asm volatile("mma.sync.aligned.m16n8k16.row.col.f32.f16.f16.f32 "
                 "{%0,%1,%2,%3}, {%4,%5,%6,%7}, {%8,%9}, {%0,%1,%2,%3};"
                 : "+f"(d[0]), "+f"(d[1]), "+f"(d[2]), "+f"(d[3])
                 : "r"(a[0]), "r"(a[1]), "r"(a[2]), "r"(a[3]), "r"(b[0]), "r"(b[1]));
}

__device__ __forceinline__ void fp16_split(float x, __half& h, __half& l) {
    h = __float2half(x);
    l = __float2half(x - __half2float(h));
}

// ---------------------------------------------------------------------------
// GEMM (NT): C[r,c] = scale * sum_k A[r,k]*B[c,k] (+bias[c])
// fp16: A 1-limb; B 1-limb (Bl==null) or 2-limb (passes a*b_h then a*b_l).
// CTA tile 256(M) x 128(N), BK=32 (last chunk may be 16), 256 threads,
// 8 warps (wm=wid&3, wn=wid>>2); per-warp nCap trims n-columns to true N.
// 3-stage cp.async pipeline; OOB B rows / OOB k-segments skip cp.async.
// REQUIRES K%16==0, M%256==0, row strides 16B-aligned.
// ---------------------------------------------------------------------------
#define ROW_B   80                     // 64B data + 16B pad (ldsm conflict-free)
#define A_TILE  (256 * ROW_B)          // 20480
#define B_TILE  (128 * ROW_B)          // 10240
#define OFF_A   0
#define OFF_BH  (A_TILE)
#define OFF_BL  (A_TILE + B_TILE)
#define STAGE_B (A_TILE + 2 * B_TILE)  // 40960
#define NSTAGE  3
#define GEMM_SMEM (NSTAGE * STAGE_B)   // 122880

__global__ void __launch_bounds__(256)
gemm_mma_kernel(const __half* __restrict__ Ah,
                const __half* __restrict__ Bh, const __half* __restrict__ Bl,
                const float* __restrict__ bias,
                float* __restrict__ Cf, __half* __restrict__ Ch, __half* __restrict__ Cl,
                int M, int N, int K, int ldc,
                long long sA, long long sB, long long sC, float scale)
{
    extern __shared__ __align__(128) char smem[];
    uint32_t smem_base = smem_to_u32(smem);
    int tid = threadIdx.x;
    int wid = tid >> 5, lane = tid & 31;
    int wm = wid & 3, wn = wid >> 2;          // 4m x 2n, SMSP-balanced trimming
    int z = blockIdx.z;
    int rowBase = blockIdx.x * 256;
    int colBase = blockIdx.y * 128;

    int rem = N - colBase - wn * 64;
    int nCap = rem >= 64 ? 8 : (rem <= 0 ? 0 : ((rem + 7) >> 3));

    const __half* pAh = Ah + (size_t)z * sA;
    const __half* pBh = Bh + (size_t)z * sB;
    const __half* pBl = Bl ? Bl + (size_t)z * sB : nullptr;

    int nChunks = (K + 31) >> 5;

    auto prefetch = [&](int c, int stage) {
        int k0 = c << 5;
        int ksegs = (K - k0) >> 3;             // 16B segments available (4 or 2)
        if (ksegs > 4) ksegs = 4;
        uint32_t sb = smem_base + stage * STAGE_B;
#pragma unroll
        for (int i = 0; i < 8; i++) {
            int s = tid + i * 256;
            if (s < 1024) {
                int r = s >> 2, cs = s & 3;
                if (cs < ksegs)
                    cp_async16(sb + OFF_A + r * ROW_B + cs * 16,
                               pAh + (size_t)(rowBase + r) * K + k0 + cs * 8);
            } else {
                int t = s - 1024;
                int limb = t >> 9, r = (t >> 2) & 127, cs = t & 3;
                int bRow = colBase + r;
                if (bRow < N && cs < ksegs && (!limb || pBl)) {
                    cp_async16(sb + (limb ? OFF_BL : OFF_BH) + r * ROW_B + cs * 16,
                               (limb ? pBl : pBh) + (size_t)bRow * K + k0 + cs * 8);
                }
            }
        }
    };

    float acc[4][8][4];
#pragma unroll
    for (int mi = 0; mi < 4; mi++)
#pragma unroll
        for (int ni = 0; ni < 8; ni++)
#pragma unroll
            for (int j = 0; j < 4; j++) acc[mi][ni][j] = 0.f;

    prefetch(0, 0); CP_COMMIT();
    if (nChunks > 1) prefetch(1, 1);
    CP_COMMIT();

#pragma unroll 1
    for (int c = 0; c < nChunks; c++) {
        int st = c % 3;
        if (c + 2 < nChunks) prefetch(c + 2, (c + 2) % 3);
        CP_COMMIT();
        CP_WAIT(2);
        __syncthreads();

        int ksMax = (K - (c << 5)) >> 4;       // 2 full, or 1 on a 16-tail chunk
        if (ksMax > 2) ksMax = 2;
        uint32_t sb = smem_base + st * STAGE_B;
#pragma unroll 1
        for (int ks = 0; ks < ksMax; ks++) {
            int kb = ks * 32;
            uint32_t ah[4][4], bcur[8][2];
#pragma unroll
            for (int mi = 0; mi < 4; mi++) {
                uint32_t addr = sb + OFF_A +
                    (uint32_t)((wm * 64 + mi * 16 + (lane & 15)) * ROW_B + ((lane >> 4) * 16) + kb);
                ldsm_x4(ah[mi], addr);
            }
            // pass 1: a * b_h
#pragma unroll
            for (int g = 0; g < 4; g++) {
                if (g * 2 < nCap) {
                    int j = lane & 7, grp = lane >> 3;
                    uint32_t addr = sb + OFF_BH +
                        (uint32_t)((wn * 64 + g * 16 + ((grp >> 1) * 8) + j) * ROW_B
                                   + ((grp & 1) * 16) + kb);
                    uint32_t r[4];
                    ldsm_x4(r, addr);
                    bcur[2*g][0] = r[0]; bcur[2*g][1] = r[1];
                    bcur[2*g+1][0] = r[2]; bcur[2*g+1][1] = r[3];
                }
            }
#pragma unroll
            for (int mi = 0; mi < 4; mi++)
#pragma unroll
                for (int ni = 0; ni < 8; ni++)
                    if (ni < nCap) mma16816h(acc[mi][ni], ah[mi], bcur[ni]);
            // pass 2: a * b_l (only when B is 2-limb)
            if (pBl) {
#pragma unroll
                for (int g = 0; g < 4; g++) {
                    if (g * 2 < nCap) {
                        int j = lane & 7, grp = lane >> 3;
                        uint32_t addr = sb + OFF_BL +
                            (uint32_t)((wn * 64 + g * 16 + ((grp >> 1) * 8) + j) * ROW_B
                                       + ((grp & 1) * 16) + kb);
                        uint32_t r[4];
                        ldsm_x4(r, addr);
                        bcur[2*g][0] = r[0]; bcur[2*g][1] = r[1];
                        bcur[2*g+1][0] = r[2]; bcur[2*g+1][1] = r[3];
                    }
                }
#pragma unroll
                for (int mi = 0; mi < 4; mi++)
#pragma unroll
                    for (int ni = 0; ni < 8; ni++)
                        if (ni < nCap) mma16816h(acc[mi][ni], ah[mi], bcur[ni]);
            }
        }
        __syncthreads();
    }

    // Epilogue: fp32 out and/or fp16 hi(+lo) out; pad cols [N, ldc) zero-filled.
    float* Cfp = Cf ? Cf + (size_t)z * sC : nullptr;
    __half* Chp = Ch ? Ch + (size_t)z * sC : nullptr;
    __half* Clp = Cl ? Cl + (size_t)z * sC : nullptr;
#pragma unroll
    for (int mi = 0; mi < 4; mi++) {
#pragma unroll
        for (int ni = 0; ni < 8; ni++) {
#pragma unroll
            for (int half = 0; half < 2; half++) {
                int gm = rowBase + wm * 64 + mi * 16 + (lane >> 2) + half * 8;
                int gn = colBase + wn * 64 + ni * 8 + 2 * (lane & 3);
                if (gn >= ldc) continue;
                size_t o = (size_t)gm * ldc + gn;
                if (gn < N) {
                    float v0 = acc[mi][ni][2*half]   * scale;
                    float v1 = acc[mi][ni][2*half+1] * scale;
                    if (bias) { v0 += bias[gn]; v1 += (gn + 1 < N) ? bias[gn+1] : 0.f; }
                    bool ok1 = (gn + 1 < N);
                    if (Cfp) {
                        Cfp[o] = v0;
                        if (ok1) Cfp[o+1] = v1;
                    }
                    if (Chp) {
                        __half hh, ll;
                        fp16_split(v0, hh, ll);
                        Chp[o] = hh; if (Clp) Clp[o] = ll;
                        if (ok1) {
                            fp16_split(v1, hh, ll);
                            Chp[o+1] = hh; if (Clp) Clp[o+1] = ll;
                        } else if (gn + 1 < ldc) {
                            Chp[o+1] = __float2half(0.f);
                            if (Clp) Clp[o+1] = __float2half(0.f);
                        }
                    }
                } else if (Chp) {
                    __half zz = __float2half(0.f);
                    Chp[o] = zz; if (Clp) Clp[o] = zz;
                    if (gn + 1 < ldc) { Chp[o+1] = zz; if (Clp) Clp[o+1] = zz; }
                }
            }
        }
    }
}

// ---------------------------------------------------------------------------
// fp32 [rows x kin] -> fp16 hi (+ optional lo) [rows x kout], pad zero.
// ---------------------------------------------------------------------------
__global__ void split_pad_kernel(const float* __restrict__ x, __half* __restrict__ h,
                                 __half* __restrict__ l, int rows, int kin, int kout)
{
    int q = kout >> 2;
    int i4 = blockIdx.x * blockDim.x + threadIdx.x;
    if (i4 >= rows * q) return;
    int r = i4 / q, c = (i4 - r * q) << 2;
    __half hv[4], lv[4];
    if (c < kin) {
        float4 v = *(const float4*)(x + (size_t)r * kin + c);
        fp16_split(v.x, hv[0], lv[0]);
        fp16_split(v.y, hv[1], lv[1]);
        fp16_split(v.z, hv[2], lv[2]);
        fp16_split(v.w, hv[3], lv[3]);
    } else {
        __half zz = __float2half(0.f);
        hv[0]=hv[1]=hv[2]=hv[3]=zz; lv[0]=lv[1]=lv[2]=lv[3]=zz;
    }
    size_t o = (size_t)r * kout + c;
    h[o]=hv[0]; h[o+1]=hv[1]; h[o+2]=hv[2]; h[o+3]=hv[3];
    if (l) { l[o]=lv[0]; l[o+1]=lv[1]; l[o+2]=lv[2]; l[o+3]=lv[3]; }
}

// concepts [b][m][300] -> ct [b][d][512] fp16 hi only
__global__ void transpose_h_kernel(const float* __restrict__ in, __half* __restrict__ oh)
{
    __shared__ float t[32][33];
    int b = blockIdx.z;
    int dBase = blockIdx.x * 32, mBase = blockIdx.y * 32;
    int tx = threadIdx.x, ty = threadIdx.y;
#pragma unroll
    for (int i = 0; i < 4; i++) {
        int m = mBase + ty + i * 8, d = dBase + tx;
        if (d < DS) t[ty + i * 8][tx] = in[((size_t)b * NS + m) * DS + d];
    }
    __syncthreads();
#pragma unroll
    for (int i = 0; i < 4; i++) {
        int d = dBase + ty + i * 8, m = mBase + tx;
        if (d < DS)
            oh[((size_t)b * DS + d) * NS + m] = __float2half(t[tx][ty + i * 8]);
    }
}

// ---------------------------------------------------------------------------
// Row softmax over N=512, output fp16 hi of probs
// ---------------------------------------------------------------------------
__global__ void softmax_h_kernel(const float* __restrict__ A, __half* __restrict__ Ph)
{
    __shared__ float sh[4];
    int row = blockIdx.x;
    const float* a = A + (size_t)row * NS;
    int tid = threadIdx.x;

    float v0 = a[tid], v1 = a[tid + 128], v2 = a[tid + 256], v3 = a[tid + 384];
    float mx = fmaxf(fmaxf(v0, v1), fmaxf(v2, v3));
#pragma unroll
    for (int o = 16; o > 0; o >>= 1) mx = fmaxf(mx, __shfl_xor_sync(0xffffffffu, mx, o));
    if ((tid & 31) == 0) sh[tid >> 5] = mx;
    __syncthreads();
    mx = fmaxf(fmaxf(sh[0], sh[1]), fmaxf(sh[2], sh[3]));
    __syncthreads();

    v0 = expf(v0 - mx); v1 = expf(v1 - mx); v2 = expf(v2 - mx); v3 = expf(v3 - mx);
    float s = v0 + v1 + v2 + v3;
#pragma unroll
    for (int o = 16; o > 0; o >>= 1) s += __shfl_xor_sync(0xffffffffu, s, o);
    if ((tid & 31) == 0) sh[tid >> 5] = s;
    __syncthreads();
    s = sh[0] + sh[1] + sh[2] + sh[3];

    float inv = 1.0f / s;
    size_t base = (size_t)row * NS;
    Ph[base + tid]       = __float2half(v0 * inv);
    Ph[base + tid + 128] = __float2half(v1 * inv);
    Ph[base + tid + 256] = __float2half(v2 * inv);
    Ph[base + tid + 384] = __float2half(v3 * inv);
}

// ---------------------------------------------------------------------------
// Mask fill + residual + LayerNorm (verified since R2)
// ---------------------------------------------------------------------------
__global__ void epilogue_kernel(const float* __restrict__ sem, const float* __restrict__ ocr,
                                const int* __restrict__ mask,
                                const float* __restrict__ lnw, const float* __restrict__ lnb,
                                float* __restrict__ out)
{
    __shared__ float sh[4];
    int row = blockIdx.x;
    int tid = threadIdx.x;
    float* y = out + (size_t)row * DS;

    if (mask[row] == 0) {
        for (int i = tid; i < DS; i += 128)
            y[i] = MASKED_CNORM * lnw[i] + lnb[i];
        return;
    }

    const float* o = ocr + (size_t)row * DS;
    const float* s = sem + (size_t)row * DS;

    float x0 = o[tid]       + s[tid];
    float x1 = o[tid + 128] + s[tid + 128];
    float x2 = 0.f;
    float sum = x0 + x1;
    if (tid < 44) { x2 = o[tid + 256] + s[tid + 256]; sum += x2; }

#pragma unroll
    for (int oo = 16; oo > 0; oo >>= 1) sum += __shfl_xor_sync(0xffffffffu, sum, oo);
    if ((tid & 31) == 0) sh[tid >> 5] = sum;
    __syncthreads();
    sum = sh[0] + sh[1] + sh[2] + sh[3];
    __syncthreads();

    float mu = sum * (1.0f / 300.0f);
    float d0 = x0 - mu, d1 = x1 - mu, d2 = (tid < 44) ? (x2 - mu) : 0.f;
    float vs = d0 * d0 + d1 * d1 + d2 * d2;
#pragma unroll
    for (int oo = 16; oo > 0; oo >>= 1) vs += __shfl_xor_sync(0xffffffffu, vs, oo);
    if ((tid & 31) == 0) sh[tid >> 5] = vs;
    __syncthreads();
    vs = sh[0] + sh[1] + sh[2] + sh[3];

    float inv = rsqrtf(vs * (1.0f / 300.0f) + 1e-5f);
    y[tid]       = d0 * inv * lnw[tid]       + lnb[tid];
    y[tid + 128] = d1 * inv * lnw[tid + 128] + lnb[tid + 128];
    if (tid < 44)
        y[tid + 256] = d2 * inv * lnw[tid + 256] + lnb[tid + 256];
}

// ---------------------------------------------------------------------------
extern "C" void kernel_launch(void* const* d_in, const int* in_sizes, int n_in,
                              void* d_out, int out_size)
{
    const float* concepts = (const float*)d_in[0];
    const float* ocr      = (const float*)d_in[1];
    const int*   mask     = (const int*)d_in[2];
    const float* wq       = (const float*)d_in[3];
    const float* bq       = (const float*)d_in[4];
    const float* wk       = (const float*)d_in[5];
    const float* bk       = (const float*)d_in[6];
    const float* lnw      = (const float*)d_in[7];
    const float* lnb      = (const float*)d_in[8];
    float* out = (float*)d_out;

    cudaFuncSetAttribute(gemm_mma_kernel, cudaFuncAttributeMaxDynamicSharedMemorySize, GEMM_SMEM);

    __half *c_h, *o_h, *ct_h, *wqh, *wql, *wkh, *wkl, *Qh, *Kh, *Kl, *Ph;
    float *A, *S;
    cudaGetSymbolAddress((void**)&c_h, g_c_h);
    cudaGetSymbolAddress((void**)&o_h, g_o_h);
    cudaGetSymbolAddress((void**)&ct_h, g_ct_h);
    cudaGetSymbolAddress((void**)&wqh, g_wq_h);   cudaGetSymbolAddress((void**)&wql, g_wq_l);
    cudaGetSymbolAddress((void**)&wkh, g_wk_h);   cudaGetSymbolAddress((void**)&wkl, g_wk_l);
    cudaGetSymbolAddress((void**)&Qh, g_Qh);
    cudaGetSymbolAddress((void**)&Kh, g_Kh);      cudaGetSymbolAddress((void**)&Kl, g_Kl);
    cudaGetSymbolAddress((void**)&Ph, g_Ph);
    cudaGetSymbolAddress((void**)&A, g_A);        cudaGetSymbolAddress((void**)&S, g_S);

    // operand splits (A-role: hi only; weights: hi+lo; ct: hi), padded [.. x 304]
    {
        int t1 = BN_ROWS * (DP / 4);
        split_pad_kernel<<<(t1 + 255) / 256, 256>>>(concepts, c_h, nullptr, BN_ROWS, DS, DP);
        split_pad_kernel<<<(t1 + 255) / 256, 256>>>(ocr,      o_h, nullptr, BN_ROWS, DS, DP);
        int t2 = DS * (DP / 4);
        split_pad_kernel<<<(t2 + 255) / 256, 256>>>(wq, wqh, wql, DS, DS, DP);
        split_pad_kernel<<<(t2 + 255) / 256, 256>>>(wk, wkh, wkl, DS, DS, DP);
        dim3 tg((DS + 31) / 32, NS / 32, BB);
        transpose_h_kernel<<<tg, dim3(32, 8)>>>(concepts, ct_h);
    }

    // Q = concepts @ wq^T + bq -> fp16 hi only, ldc=304
    gemm_mma_kernel<<<dim3(BN_ROWS / 256, 3, 1), 256, GEMM_SMEM>>>(
        c_h, wqh, wql, bq, nullptr, Qh, nullptr,
        BN_ROWS, DS, DP, DP, 0, 0, 0, 1.0f);
    // K = ocr @ wk^T + bk -> fp16 hi+lo
    gemm_mma_kernel<<<dim3(BN_ROWS / 256, 3, 1), 256, GEMM_SMEM>>>(
        o_h, wkh, wkl, bk, nullptr, Kh, Kl,
        BN_ROWS, DS, DP, DP, 0, 0, 0, 1.0f);

    // scores[b] = (Q K^T)/sqrt(D)   fp32   (K=304)
    gemm_mma_kernel<<<dim3(NS / 256, NS / 128, BB), 256, GEMM_SMEM>>>(
        Qh, Kh, Kl, nullptr, A, nullptr, nullptr,
        NS, NS, DP, NS,
        (long long)NS * DP, (long long)NS * DP, (long long)NS * NS, INV_SQRT_D);

    // softmax -> P fp16 hi
    softmax_h_kernel<<<BN_ROWS, 128>>>(A, Ph);

    // sem[b] = P @ concepts[b]  (B = concepts^T, 1-limb, NT, K=512)   fp32
    gemm_mma_kernel<<<dim3(NS / 256, 3, BB), 256, GEMM_SMEM>>>(
        Ph, ct_h, nullptr, nullptr, S, nullptr, nullptr,
        NS, DS, NS, DS,
        (long long)NS * NS, (long long)DS * NS, (long long)NS * DS, 1.0f);

    // mask + residual + LayerNorm
    epilogue_kernel<<<BN_ROWS, 128>>>(S, ocr, mask, lnw, lnb, out);

    (void)in_sizes; (void)n_in; (void)out_size;
}

// round 12
// speedup vs baseline: 3.3485x; 1.2623x over previous
#include <cuda_runtime.h>
#include <cuda_fp16.h>
#include <cstdint>

#define BB 64
#define NS 512
#define DS 300
#define DP 304                          // K padded to multiple of 16
#define BN_ROWS (BB*NS)                 // 32768
#define INV_SQRT_D 0.057735026918962576f
#define MASKED_CNORM (1.0f)

// ---------------------------------------------------------------------------
// Device-global scratch (runtime allocation forbidden); 16B-aligned rows
// (row strides 608B / 1024B, both %16==0). All operands single-limb fp16.
// ---------------------------------------------------------------------------
__device__ alignas(1024) __half g_c_h[(size_t)BN_ROWS * DP];     // concepts fp16
__device__ alignas(1024) __half g_o_h[(size_t)BN_ROWS * DP];     // ocr fp16
__device__ alignas(1024) __half g_ct_h[(size_t)BB * DS * NS];    // concepts^T fp16
__device__ alignas(1024) __half g_wq_h[DS * DP];                 // weights fp16
__device__ alignas(1024) __half g_wk_h[DS * DP];
__device__ alignas(1024) __half g_Qh[(size_t)BN_ROWS * DP];      // Q fp16
__device__ alignas(1024) __half g_Kh[(size_t)BN_ROWS * DP];      // K fp16
__device__ alignas(1024) __half g_Ph[(size_t)BB * NS * NS];      // P fp16
__device__ alignas(1024) float  g_A[(size_t)BB * NS * NS];       // scores fp32
__device__ alignas(1024) float  g_S[(size_t)BN_ROWS * DS];       // semantic fp32

// ---------------------------------------------------------------------------
// PTX helpers (sm_80-era only; compiles under compute_103)
// ---------------------------------------------------------------------------
__device__ __forceinline__ uint32_t smem_to_u32(const void* p) {
    uint32_t a;
    asm("{ .reg .u64 t; cvta.to.shared.u64 t, %1; cvt.u32.u64 %0, t; }" : "=r"(a) : "l"(p));
    return a;
}
__device__ __forceinline__ void cp_async16(uint32_t dst, const void* src) {
    asm volatile("cp.async.cg.shared.global [%0], [%1], 16;"
                 :: "r"(dst), "l"(src) : "memory");
}
#define CP_COMMIT() asm volatile("cp.async.commit_group;" ::: "memory")
#define CP_WAIT(n)  asm volatile("cp.async.wait_group %0;" :: "n"(n) : "memory")

__device__ __forceinline__ void ldsm_x4(uint32_t* r, uint32_t addr) {
    asm volatile("ldmatrix.sync.aligned.m8n8.x4.shared.b16 {%0,%1,%2,%3}, [%4];"
                 : "=r"(r[0]), "=r"(r[1]), "=r"(r[2]), "=r"(r[3]) : "r"(addr));
}
__device__ __forceinline__ void mma16816h(float* d, const uint32_t* a, const uint32_t* b) {
    asm volatile("mma.sync.aligned.m16n8k16.row.col.f32.f16.f16.f32 "
                 "{%0,%1,%2,%3}, {%4,%5,%6,%7}, {%8,%9}, {%0,%1,%2,%3};"
                 : "+f"(d[0]), "+f"(d[1]), "+f"(d[2]), "+f"(d[3])
                 : "r"(a[0]), "r"(a[1]), "r"(a[2]), "r"(a[3]), "r"(b[0]), "r"(b[1]));
}

// ---------------------------------------------------------------------------
// GEMM (NT): C[r,c] = scale * sum_k A[r,k]*B[c,k] (+bias[c]), fp16 single-pass.
// CTA tile 256(M) x 128(N), BK=32 (last chunk may be 16), 256 threads,
// 8 warps (wm=wid&3, wn=wid>>2); per-warp nCap trims n-columns to true N.
// 3-stage cp.async pipeline; OOB B rows / OOB k-segments skip cp.async.
// REQUIRES K%16==0, M%256==0, row strides 16B-aligned.
// ---------------------------------------------------------------------------
#define ROW_B   80                     // 64B data + 16B pad (ldsm conflict-free)
#define A_TILE  (256 * ROW_B)          // 20480
#define B_TILE  (128 * ROW_B)          // 10240
#define OFF_A   0
#define OFF_B   (A_TILE)
#define STAGE_B (A_TILE + B_TILE)      // 30720
#define NSTAGE  3
#define GEMM_SMEM (NSTAGE * STAGE_B)   // 92160

__global__ void __launch_bounds__(256)
gemm_mma_kernel(const __half* __restrict__ Ah, const __half* __restrict__ Bh,
                const float* __restrict__ bias,
                float* __restrict__ Cf, __half* __restrict__ Ch,
                int M, int N, int K, int ldc,
                long long sA, long long sB, long long sC, float scale)
{
    extern __shared__ __align__(128) char smem[];
    uint32_t smem_base = smem_to_u32(smem);
    int tid = threadIdx.x;
    int wid = tid >> 5, lane = tid & 31;
    int wm = wid & 3, wn = wid >> 2;          // 4m x 2n, SMSP-balanced trimming
    int z = blockIdx.z;
    int rowBase = blockIdx.x * 256;
    int colBase = blockIdx.y * 128;

    int rem = N - colBase - wn * 64;
    int nCap = rem >= 64 ? 8 : (rem <= 0 ? 0 : ((rem + 7) >> 3));

    const __half* pAh = Ah + (size_t)z * sA;
    const __half* pBh = Bh + (size_t)z * sB;

    int nChunks = (K + 31) >> 5;

    // 1536 16B-segments per chunk: A 1024 (256 rows x 4), B 512 (128 rows x 4)
    auto prefetch = [&](int c, int stage) {
        int k0 = c << 5;
        int ksegs = (K - k0) >> 3;             // 4, or 2 on the 16-tail chunk
        if (ksegs > 4) ksegs = 4;
        uint32_t sb = smem_base + stage * STAGE_B;
#pragma unroll
        for (int i = 0; i < 6; i++) {
            int s = tid + i * 256;
            if (s < 1024) {
                int r = s >> 2, cs = s & 3;
                if (cs < ksegs)
                    cp_async16(sb + OFF_A + r * ROW_B + cs * 16,
                               pAh + (size_t)(rowBase + r) * K + k0 + cs * 8);
            } else {
                int t = s - 1024;
                int r = t >> 2, cs = t & 3;
                int bRow = colBase + r;
                if (bRow < N && cs < ksegs)
                    cp_async16(sb + OFF_B + r * ROW_B + cs * 16,
                               pBh + (size_t)bRow * K + k0 + cs * 8);
            }
        }
    };

    float acc[4][8][4];
#pragma unroll
    for (int mi = 0; mi < 4; mi++)
#pragma unroll
        for (int ni = 0; ni < 8; ni++)
#pragma unroll
            for (int j = 0; j < 4; j++) acc[mi][ni][j] = 0.f;

    prefetch(0, 0); CP_COMMIT();
    if (nChunks > 1) prefetch(1, 1);
    CP_COMMIT();

#pragma unroll 1
    for (int c = 0; c < nChunks; c++) {
        int st = c % 3;
        if (c + 2 < nChunks) prefetch(c + 2, (c + 2) % 3);
        CP_COMMIT();
        CP_WAIT(2);
        __syncthreads();

        int ksMax = (K - (c << 5)) >> 4;       // 2 full, or 1 on 16-tail chunk
        if (ksMax > 2) ksMax = 2;
        uint32_t sb = smem_base + st * STAGE_B;
#pragma unroll 1
        for (int ks = 0; ks < ksMax; ks++) {
            int kb = ks * 32;
            uint32_t ah[4][4], bcur[8][2];
#pragma unroll
            for (int mi = 0; mi < 4; mi++) {
                uint32_t addr = sb + OFF_A +
                    (uint32_t)((wm * 64 + mi * 16 + (lane & 15)) * ROW_B + ((lane >> 4) * 16) + kb);
                ldsm_x4(ah[mi], addr);
            }
#pragma unroll
            for (int g = 0; g < 4; g++) {
                if (g * 2 < nCap) {
                    int j = lane & 7, grp = lane >> 3;
                    uint32_t addr = sb + OFF_B +
                        (uint32_t)((wn * 64 + g * 16 + ((grp >> 1) * 8) + j) * ROW_B
                                   + ((grp & 1) * 16) + kb);
                    uint32_t r[4];
                    ldsm_x4(r, addr);
                    bcur[2*g][0] = r[0]; bcur[2*g][1] = r[1];
                    bcur[2*g+1][0] = r[2]; bcur[2*g+1][1] = r[3];
                }
            }
#pragma unroll
            for (int mi = 0; mi < 4; mi++)
#pragma unroll
                for (int ni = 0; ni < 8; ni++)
                    if (ni < nCap) mma16816h(acc[mi][ni], ah[mi], bcur[ni]);
        }
        __syncthreads();
    }

    // Epilogue: fp32 out and/or fp16 out; pad cols [N, ldc) zero-filled.
    float* Cfp = Cf ? Cf + (size_t)z * sC : nullptr;
    __half* Chp = Ch ? Ch + (size_t)z * sC : nullptr;
#pragma unroll
    for (int mi = 0; mi < 4; mi++) {
#pragma unroll
        for (int ni = 0; ni < 8; ni++) {
#pragma unroll
            for (int half = 0; half < 2; half++) {
                int gm = rowBase + wm * 64 + mi * 16 + (lane >> 2) + half * 8;
                int gn = colBase + wn * 64 + ni * 8 + 2 * (lane & 3);
                if (gn >= ldc) continue;
                size_t o = (size_t)gm * ldc + gn;
                if (gn < N) {
                    float v0 = acc[mi][ni][2*half]   * scale;
                    float v1 = acc[mi][ni][2*half+1] * scale;
                    if (bias) { v0 += bias[gn]; v1 += (gn + 1 < N) ? bias[gn+1] : 0.f; }
                    bool ok1 = (gn + 1 < N);
                    if (Cfp) {
                        Cfp[o] = v0;
                        if (ok1) Cfp[o+1] = v1;
                    }
                    if (Chp) {
                        Chp[o] = __float2half(v0);
                        if (ok1) Chp[o+1] = __float2half(v1);
                        else if (gn + 1 < ldc) Chp[o+1] = __float2half(0.f);
                    }
                } else if (Chp) {
                    Chp[o] = __float2half(0.f);
                    if (gn + 1 < ldc) Chp[o+1] = __float2half(0.f);
                }
            }
        }
    }
}

// ---------------------------------------------------------------------------
// fp32 [rows x kin] -> fp16 [rows x kout], pad zero.
// ---------------------------------------------------------------------------
__global__ void cvt_pad_kernel(const float* __restrict__ x, __half* __restrict__ h,
                               int rows, int kin, int kout)
{
    int q = kout >> 2;
    int i4 = blockIdx.x * blockDim.x + threadIdx.x;
    if (i4 >= rows * q) return;
    int r = i4 / q, c = (i4 - r * q) << 2;
    __half hv[4];
    if (c < kin) {
        float4 v = *(const float4*)(x + (size_t)r * kin + c);
        hv[0] = __float2half(v.x); hv[1] = __float2half(v.y);
        hv[2] = __float2half(v.z); hv[3] = __float2half(v.w);
    } else {
        __half zz = __float2half(0.f);
        hv[0]=hv[1]=hv[2]=hv[3]=zz;
    }
    size_t o = (size_t)r * kout + c;
    h[o]=hv[0]; h[o+1]=hv[1]; h[o+2]=hv[2]; h[o+3]=hv[3];
}

// concepts [b][m][300] -> ct [b][d][512] fp16
__global__ void transpose_h_kernel(const float* __restrict__ in, __half* __restrict__ oh)
{
    __shared__ float t[32][33];
    int b = blockIdx.z;
    int dBase = blockIdx.x * 32, mBase = blockIdx.y * 32;
    int tx = threadIdx.x, ty = threadIdx.y;
#pragma unroll
    for (int i = 0; i < 4; i++) {
        int m = mBase + ty + i * 8, d = dBase + tx;
        if (d < DS) t[ty + i * 8][tx] = in[((size_t)b * NS + m) * DS + d];
    }
    __syncthreads();
#pragma unroll
    for (int i = 0; i < 4; i++) {
        int d = dBase + ty + i * 8, m = mBase + tx;
        if (d < DS)
            oh[((size_t)b * DS + d) * NS + m] = __float2half(t[tx][ty + i * 8]);
    }
}

// ---------------------------------------------------------------------------
// Row softmax over N=512, output fp16 probs
// ---------------------------------------------------------------------------
__global__ void softmax_h_kernel(const float* __restrict__ A, __half* __restrict__ Ph)
{
    __shared__ float sh[4];
    int row = blockIdx.x;
    const float* a = A + (size_t)row * NS;
    int tid = threadIdx.x;

    float v0 = a[tid], v1 = a[tid + 128], v2 = a[tid + 256], v3 = a[tid + 384];
    float mx = fmaxf(fmaxf(v0, v1), fmaxf(v2, v3));
#pragma unroll
    for (int o = 16; o > 0; o >>= 1) mx = fmaxf(mx, __shfl_xor_sync(0xffffffffu, mx, o));
    if ((tid & 31) == 0) sh[tid >> 5] = mx;
    __syncthreads();
    mx = fmaxf(fmaxf(sh[0], sh[1]), fmaxf(sh[2], sh[3]));
    __syncthreads();

    v0 = expf(v0 - mx); v1 = expf(v1 - mx); v2 = expf(v2 - mx); v3 = expf(v3 - mx);
    float s = v0 + v1 + v2 + v3;
#pragma unroll
    for (int o = 16; o > 0; o >>= 1) s += __shfl_xor_sync(0xffffffffu, s, o);
    if ((tid & 31) == 0) sh[tid >> 5] = s;
    __syncthreads();
    s = sh[0] + sh[1] + sh[2] + sh[3];

    float inv = 1.0f / s;
    size_t base = (size_t)row * NS;
    Ph[base + tid]       = __float2half(v0 * inv);
    Ph[base + tid + 128] = __float2half(v1 * inv);
    Ph[base + tid + 256] = __float2half(v2 * inv);
    Ph[base + tid + 384] = __float2half(v3 * inv);
}

// ---------------------------------------------------------------------------
// Mask fill + residual + LayerNorm (verified since R2)
// ---------------------------------------------------------------------------
__global__ void epilogue_kernel(const float* __restrict__ sem, const float* __restrict__ ocr,
                                const int* __restrict__ mask,
                                const float* __restrict__ lnw, const float* __restrict__ lnb,
                                float* __restrict__ out)
{
    __shared__ float sh[4];
    int row = blockIdx.x;
    int tid = threadIdx.x;
    float* y = out + (size_t)row * DS;

    if (mask[row] == 0) {
        for (int i = tid; i < DS; i += 128)
            y[i] = MASKED_CNORM * lnw[i] + lnb[i];
        return;
    }

    const float* o = ocr + (size_t)row * DS;
    const float* s = sem + (size_t)row * DS;

    float x0 = o[tid]       + s[tid];
    float x1 = o[tid + 128] + s[tid + 128];
    float x2 = 0.f;
    float sum = x0 + x1;
    if (tid < 44) { x2 = o[tid + 256] + s[tid + 256]; sum += x2; }

#pragma unroll
    for (int oo = 16; oo > 0; oo >>= 1) sum += __shfl_xor_sync(0xffffffffu, sum, oo);
    if ((tid & 31) == 0) sh[tid >> 5] = sum;
    __syncthreads();
    sum = sh[0] + sh[1] + sh[2] + sh[3];
    __syncthreads();

    float mu = sum * (1.0f / 300.0f);
    float d0 = x0 - mu, d1 = x1 - mu, d2 = (tid < 44) ? (x2 - mu) : 0.f;
    float vs = d0 * d0 + d1 * d1 + d2 * d2;
#pragma unroll
    for (int oo = 16; oo > 0; oo >>= 1) vs += __shfl_xor_sync(0xffffffffu, vs, oo);
    if ((tid & 31) == 0) sh[tid >> 5] = vs;
    __syncthreads();
    vs = sh[0] + sh[1] + sh[2] + sh[3];

    float inv = rsqrtf(vs * (1.0f / 300.0f) + 1e-5f);
    y[tid]       = d0 * inv * lnw[tid]       + lnb[tid];
    y[tid + 128] = d1 * inv * lnw[tid + 128] + lnb[tid + 128];
    if (tid < 44)
        y[tid + 256] = d2 * inv * lnw[tid + 256] + lnb[tid + 256];
}

// ---------------------------------------------------------------------------
extern "C" void kernel_launch(void* const* d_in, const int* in_sizes, int n_in,
                              void* d_out, int out_size)
{
    const float* concepts = (const float*)d_in[0];
    const float* ocr      = (const float*)d_in[1];
    const int*   mask     = (const int*)d_in[2];
    const float* wq       = (const float*)d_in[3];
    const float* bq       = (const float*)d_in[4];
    const float* wk       = (const float*)d_in[5];
    const float* bk       = (const float*)d_in[6];
    const float* lnw      = (const float*)d_in[7];
    const float* lnb      = (const float*)d_in[8];
    float* out = (float*)d_out;

    cudaFuncSetAttribute(gemm_mma_kernel, cudaFuncAttributeMaxDynamicSharedMemorySize, GEMM_SMEM);

    __half *c_h, *o_h, *ct_h, *wqh, *wkh, *Qh, *Kh, *Ph;
    float *A, *S;
    cudaGetSymbolAddress((void**)&c_h, g_c_h);
    cudaGetSymbolAddress((void**)&o_h, g_o_h);
    cudaGetSymbolAddress((void**)&ct_h, g_ct_h);
    cudaGetSymbolAddress((void**)&wqh, g_wq_h);
    cudaGetSymbolAddress((void**)&wkh, g_wk_h);
    cudaGetSymbolAddress((void**)&Qh, g_Qh);
    cudaGetSymbolAddress((void**)&Kh, g_Kh);
    cudaGetSymbolAddress((void**)&Ph, g_Ph);
    cudaGetSymbolAddress((void**)&A, g_A);
    cudaGetSymbolAddress((void**)&S, g_S);

    // fp16 conversions (padded [.. x 304])
    {
        int t1 = BN_ROWS * (DP / 4);
        cvt_pad_kernel<<<(t1 + 255) / 256, 256>>>(concepts, c_h, BN_ROWS, DS, DP);
        cvt_pad_kernel<<<(t1 + 255) / 256, 256>>>(ocr,      o_h, BN_ROWS, DS, DP);
        int t2 = DS * (DP / 4);
        cvt_pad_kernel<<<(t2 + 255) / 256, 256>>>(wq, wqh, DS, DS, DP);
        cvt_pad_kernel<<<(t2 + 255) / 256, 256>>>(wk, wkh, DS, DS, DP);
        dim3 tg((DS + 31) / 32, NS / 32, BB);
        transpose_h_kernel<<<tg, dim3(32, 8)>>>(concepts, ct_h);
    }

    // Q = concepts @ wq^T + bq -> fp16, ldc=304
    gemm_mma_kernel<<<dim3(BN_ROWS / 256, 3, 1), 256, GEMM_SMEM>>>(
        c_h, wqh, bq, nullptr, Qh,
        BN_ROWS, DS, DP, DP, 0, 0, 0, 1.0f);
    // K = ocr @ wk^T + bk -> fp16
    gemm_mma_kernel<<<dim3(BN_ROWS / 256, 3, 1), 256, GEMM_SMEM>>>(
        o_h, wkh, bk, nullptr, Kh,
        BN_ROWS, DS, DP, DP, 0, 0, 0, 1.0f);

    // scores[b] = (Q K^T)/sqrt(D)   fp32   (K=304)
    gemm_mma_kernel<<<dim3(NS / 256, NS / 128, BB), 256, GEMM_SMEM>>>(
        Qh, Kh, nullptr, A, nullptr,
        NS, NS, DP, NS,
        (long long)NS * DP, (long long)NS * DP, (long long)NS * NS, INV_SQRT_D);

    // softmax -> P fp16
    softmax_h_kernel<<<BN_ROWS, 128>>>(A, Ph);

    // sem[b] = P @ concepts[b]  (B = concepts^T, NT, K=512)   fp32
    gemm_mma_kernel<<<dim3(NS / 256, 3, BB), 256, GEMM_SMEM>>>(
        Ph, ct_h, nullptr, S, nullptr,
        NS, DS, NS, DS,
        (long long)NS * NS, (long long)DS * NS, (long long)NS * DS, 1.0f);

    // mask + residual + LayerNorm
    epilogue_kernel<<<BN_ROWS, 128>>>(S, ocr, mask, lnw, lnb, out);

    (void)in_sizes; (void)n_in; (void)out_size;
}

// round 13
// speedup vs baseline: 3.5664x; 1.0651x over previous
#include <cuda_runtime.h>
#include <cuda_fp16.h>
#include <cstdint>

#define BB 64
#define NS 512
#define DS 300
#define DP 304                          // K padded to multiple of 16
#define BN_ROWS (BB*NS)                 // 32768
#define INV_SQRT_D 0.057735026918962576f
#define MASKED_CNORM (1.0f)

// ---------------------------------------------------------------------------
// Device-global scratch (runtime allocation forbidden); 16B-aligned rows.
// ---------------------------------------------------------------------------
__device__ alignas(1024) __half g_c_h[(size_t)BN_ROWS * DP];     // concepts fp16
__device__ alignas(1024) __half g_o_h[(size_t)BN_ROWS * DP];     // ocr fp16
__device__ alignas(1024) __half g_ct_h[(size_t)BB * DS * NS];    // concepts^T fp16
__device__ alignas(1024) __half g_wq_h[DS * DP];
__device__ alignas(1024) __half g_wk_h[DS * DP];
__device__ alignas(1024) __half g_Qh[(size_t)BN_ROWS * DP];
__device__ alignas(1024) __half g_Kh[(size_t)BN_ROWS * DP];
__device__ alignas(1024) __half g_Ph[(size_t)BB * NS * NS];
__device__ alignas(1024) float  g_A[(size_t)BB * NS * NS];       // scores fp32
__device__ alignas(1024) float  g_S[(size_t)BN_ROWS * DS];       // semantic fp32

// ---------------------------------------------------------------------------
// PTX helpers (sm_80-era only; compiles under compute_103)
// ---------------------------------------------------------------------------
__device__ __forceinline__ uint32_t smem_to_u32(const void* p) {
    uint32_t a;
    asm("{ .reg .u64 t; cvta.to.shared.u64 t, %1; cvt.u32.u64 %0, t; }" : "=r"(a) : "l"(p));
    return a;
}
__device__ __forceinline__ void cp_async16(uint32_t dst, const void* src) {
    asm volatile("cp.async.cg.shared.global [%0], [%1], 16;"
                 :: "r"(dst), "l"(src) : "memory");
}
#define CP_COMMIT() asm volatile("cp.async.commit_group;" ::: "memory")
#define CP_WAIT(n)  asm volatile("cp.async.wait_group %0;" :: "n"(n) : "memory")

__device__ __forceinline__ void ldsm_x4(uint32_t* r, uint32_t addr) {
    asm volatile("ldmatrix.sync.aligned.m8n8.x4.shared.b16 {%0,%1,%2,%3}, [%4];"
                 : "=r"(r[0]), "=r"(r[1]), "=r"(r[2]), "=r"(r[3]) : "r"(addr));
}
__device__ __forceinline__ void mma16816h(float* d, const uint32_t* a, const uint32_t* b) {
    asm volatile("mma.sync.aligned.m16n8k16.row.col.f32.f16.f16.f32 "
                 "{%0,%1,%2,%3}, {%4,%5,%6,%7}, {%8,%9}, {%0,%1,%2,%3};"
                 : "+f"(d[0]), "+f"(d[1]), "+f"(d[2]), "+f"(d[3])
                 : "r"(a[0]), "r"(a[1]), "r"(a[2]), "r"(a[3]), "r"(b[0]), "r"(b[1]));
}

// ---------------------------------------------------------------------------
// A-resident GEMM (NT): C[r,c] = scale * sum_k A[r,k]*B[c,k] (+bias[c]).
// A slab (MTILE x K fp16, row stride K*2+16 B) loaded to SMEM ONCE, then the
// CTA loops nTiles n-tiles of 128 cols; per n-tile a 3-stage cp.async pipeline
// stages only B chunks (128 rows x 32 k). 256 threads, 8 warps (4m x 2n),
// MI = m-frags per warp (MTILE = MI*64). Per-warp nCap trims to true N.
// Proj fusion: if Ah2 != null, blockIdx.z selects operand set {A,bias,Ch}.
// REQUIRES K%16==0, M%MTILE==0, 16B-aligned rows.
// ---------------------------------------------------------------------------
#define ROW_B   80
#define B_TILE  (128 * ROW_B)          // 10240
#define NSTAGE  3

template<int MI>
__global__ void __launch_bounds__(256)
gemm_ar_kernel(const __half* __restrict__ Ah, const __half* __restrict__ Ah2,
               const __half* __restrict__ Bh,
               const float* __restrict__ bias, const float* __restrict__ bias2,
               float* __restrict__ Cf, __half* __restrict__ Ch, __half* __restrict__ Ch2,
               int M, int N, int K, int ldc, int nTiles,
               long long sA, long long sB, long long sC, float scale)
{
    constexpr int MTILE = MI * 64;
    extern __shared__ __align__(128) char smem[];
    uint32_t smem_base = smem_to_u32(smem);
    int tid = threadIdx.x;
    int wid = tid >> 5, lane = tid & 31;
    int wm = wid & 3, wn = wid >> 2;
    int z = blockIdx.z;
    int rowBase = blockIdx.x * MTILE;
    int colBase0 = blockIdx.y * (nTiles * 128);

    const int strideA = K * 2 + 16;                 // bytes, %16==0
    const uint32_t aSize = (uint32_t)MTILE * strideA;
    const int segsPerRow = K >> 3;                  // 16B segs per A row

    // Operand-set select (proj fusion) or batched strides
    const __half* pA;
    const float* pb;
    float* pCf;
    __half* pCh;
    if (Ah2) {
        pA  = z ? Ah2 : Ah;
        pb  = z ? bias2 : bias;
        pCh = z ? Ch2 : Ch;
        pCf = nullptr;
    } else {
        pA  = Ah + (size_t)z * sA;
        pb  = bias;
        pCf = Cf ? Cf + (size_t)z * sC : nullptr;
        pCh = Ch ? Ch + (size_t)z * sC : nullptr;
    }
    const __half* pB = Bh + (size_t)z * sB;

    // ---- Load A slab into SMEM (one group) ----
    {
        int total = MTILE * segsPerRow;
        for (int s = tid; s < total; s += 256) {
            int r = s / segsPerRow, cs = s - r * segsPerRow;
            cp_async16(smem_base + (uint32_t)r * strideA + cs * 16,
                       pA + (size_t)(rowBase + r) * K + cs * 8);
        }
        CP_COMMIT();
    }

    int nChunks = (K + 31) >> 5;

    auto prefB = [&](int c, int stage, int colBase) {
        int k0 = c << 5;
        int ksegs = (K - k0) >> 3;
        if (ksegs > 4) ksegs = 4;
        uint32_t sb = smem_base + aSize + stage * B_TILE;
#pragma unroll
        for (int i = 0; i < 2; i++) {
            int s = tid + i * 256;                 // 0..511: 128 rows x 4 segs
            int r = s >> 2, cs = s & 3;
            int bRow = colBase + r;
            if (bRow < N && cs < ksegs)
                cp_async16(sb + r * ROW_B + cs * 16,
                           pB + (size_t)bRow * K + k0 + cs * 8);
        }
    };

#pragma unroll 1
    for (int nt = 0; nt < nTiles; nt++) {
        int colBase = colBase0 + nt * 128;
        int rem = N - colBase - wn * 64;
        int nCap = rem >= 64 ? 8 : (rem <= 0 ? 0 : ((rem + 7) >> 3));

        float acc[MI][8][4];
#pragma unroll
        for (int mi = 0; mi < MI; mi++)
#pragma unroll
            for (int ni = 0; ni < 8; ni++)
#pragma unroll
                for (int j = 0; j < 4; j++) acc[mi][ni][j] = 0.f;

        prefB(0, 0, colBase); CP_COMMIT();
        if (nChunks > 1) prefB(1, 1, colBase);
        CP_COMMIT();

#pragma unroll 1
        for (int c = 0; c < nChunks; c++) {
            int st = c % 3;
            if (c + 2 < nChunks) prefB(c + 2, (c + 2) % 3, colBase);
            CP_COMMIT();
            CP_WAIT(2);                 // chunk c's B (and, on nt=0,c=0, the A slab) done
            __syncthreads();

            int ksMax = (K - (c << 5)) >> 4;
            if (ksMax > 2) ksMax = 2;
            uint32_t sbB = smem_base + aSize + st * B_TILE;
#pragma unroll 1
            for (int ks = 0; ks < ksMax; ks++) {
                int kstep = c * 2 + ks;
                uint32_t ah[MI][4], bcur[8][2];
#pragma unroll
                for (int mi = 0; mi < MI; mi++) {
                    uint32_t addr = smem_base +
                        (uint32_t)((wm * (MI * 16) + mi * 16 + (lane & 15)) * strideA)
                        + ((lane >> 4) * 16) + kstep * 32;
                    ldsm_x4(ah[mi], addr);
                }
#pragma unroll
                for (int g = 0; g < 4; g++) {
                    if (g * 2 < nCap) {
                        int j = lane & 7, grp = lane >> 3;
                        uint32_t addr = sbB +
                            (uint32_t)((wn * 64 + g * 16 + ((grp >> 1) * 8) + j) * ROW_B
                                       + ((grp & 1) * 16) + ks * 32);
                        uint32_t r[4];
                        ldsm_x4(r, addr);
                        bcur[2*g][0] = r[0]; bcur[2*g][1] = r[1];
                        bcur[2*g+1][0] = r[2]; bcur[2*g+1][1] = r[3];
                    }
                }
#pragma unroll
                for (int mi = 0; mi < MI; mi++)
#pragma unroll
                    for (int ni = 0; ni < 8; ni++)
                        if (ni < nCap) mma16816h(acc[mi][ni], ah[mi], bcur[ni]);
            }
            __syncthreads();
        }

        // Epilogue for this n-tile
#pragma unroll
        for (int mi = 0; mi < MI; mi++) {
#pragma unroll
            for (int ni = 0; ni < 8; ni++) {
#pragma unroll
                for (int half = 0; half < 2; half++) {
                    int gm = rowBase + wm * (MI * 16) + mi * 16 + (lane >> 2) + half * 8;
                    int gn = colBase + wn * 64 + ni * 8 + 2 * (lane & 3);
                    if (gn >= ldc) continue;
                    size_t o = (size_t)gm * ldc + gn;
                    if (gn < N) {
                        float v0 = acc[mi][ni][2*half]   * scale;
                        float v1 = acc[mi][ni][2*half+1] * scale;
                        if (pb) { v0 += pb[gn]; v1 += (gn + 1 < N) ? pb[gn+1] : 0.f; }
                        bool ok1 = (gn + 1 < N);
                        if (pCf) {
                            pCf[o] = v0;
                            if (ok1) pCf[o+1] = v1;
                        }
                        if (pCh) {
                            pCh[o] = __float2half(v0);
                            if (ok1) pCh[o+1] = __float2half(v1);
                            else if (gn + 1 < ldc) pCh[o+1] = __float2half(0.f);
                        }
                    } else if (pCh) {
                        pCh[o] = __float2half(0.f);
                        if (gn + 1 < ldc) pCh[o+1] = __float2half(0.f);
                    }
                }
            }
        }
        CP_WAIT(0);
        __syncthreads();
    }
}

// ---------------------------------------------------------------------------
// fp32 [rows x kin] -> fp16 [rows x kout], pad zero.
// ---------------------------------------------------------------------------
__global__ void cvt_pad_kernel(const float* __restrict__ x, __half* __restrict__ h,
                               int rows, int kin, int kout)
{
    int q = kout >> 2;
    int i4 = blockIdx.x * blockDim.x + threadIdx.x;
    if (i4 >= rows * q) return;
    int r = i4 / q, c = (i4 - r * q) << 2;
    __half hv[4];
    if (c < kin) {
        float4 v = *(const float4*)(x + (size_t)r * kin + c);
        hv[0] = __float2half(v.x); hv[1] = __float2half(v.y);
        hv[2] = __float2half(v.z); hv[3] = __float2half(v.w);
    } else {
        __half zz = __float2half(0.f);
        hv[0]=hv[1]=hv[2]=hv[3]=zz;
    }
    size_t o = (size_t)r * kout + c;
    h[o]=hv[0]; h[o+1]=hv[1]; h[o+2]=hv[2]; h[o+3]=hv[3];
}

// concepts [b][m][300] -> ct [b][d][512] fp16
__global__ void transpose_h_kernel(const float* __restrict__ in, __half* __restrict__ oh)
{
    __shared__ float t[32][33];
    int b = blockIdx.z;
    int dBase = blockIdx.x * 32, mBase = blockIdx.y * 32;
    int tx = threadIdx.x, ty = threadIdx.y;
#pragma unroll
    for (int i = 0; i < 4; i++) {
        int m = mBase + ty + i * 8, d = dBase + tx;
        if (d < DS) t[ty + i * 8][tx] = in[((size_t)b * NS + m) * DS + d];
    }
    __syncthreads();
#pragma unroll
    for (int i = 0; i < 4; i++) {
        int d = dBase + ty + i * 8, m = mBase + tx;
        if (d < DS)
            oh[((size_t)b * DS + d) * NS + m] = __float2half(t[tx][ty + i * 8]);
    }
}

// ---------------------------------------------------------------------------
// Row softmax over N=512, output fp16 probs
// ---------------------------------------------------------------------------
__global__ void softmax_h_kernel(const float* __restrict__ A, __half* __restrict__ Ph)
{
    __shared__ float sh[4];
    int row = blockIdx.x;
    const float* a = A + (size_t)row * NS;
    int tid = threadIdx.x;

    float v0 = a[tid], v1 = a[tid + 128], v2 = a[tid + 256], v3 = a[tid + 384];
    float mx = fmaxf(fmaxf(v0, v1), fmaxf(v2, v3));
#pragma unroll
    for (int o = 16; o > 0; o >>= 1) mx = fmaxf(mx, __shfl_xor_sync(0xffffffffu, mx, o));
    if ((tid & 31) == 0) sh[tid >> 5] = mx;
    __syncthreads();
    mx = fmaxf(fmaxf(sh[0], sh[1]), fmaxf(sh[2], sh[3]));
    __syncthreads();

    v0 = expf(v0 - mx); v1 = expf(v1 - mx); v2 = expf(v2 - mx); v3 = expf(v3 - mx);
    float s = v0 + v1 + v2 + v3;
#pragma unroll
    for (int o = 16; o > 0; o >>= 1) s += __shfl_xor_sync(0xffffffffu, s, o);
    if ((tid & 31) == 0) sh[tid >> 5] = s;
    __syncthreads();
    s = sh[0] + sh[1] + sh[2] + sh[3];

    float inv = 1.0f / s;
    size_t base = (size_t)row * NS;
    Ph[base + tid]       = __float2half(v0 * inv);
    Ph[base + tid + 128] = __float2half(v1 * inv);
    Ph[base + tid + 256] = __float2half(v2 * inv);
    Ph[base + tid + 384] = __float2half(v3 * inv);
}

// ---------------------------------------------------------------------------
// Mask fill + residual + LayerNorm (verified since R2)
// ---------------------------------------------------------------------------
__global__ void epilogue_kernel(const float* __restrict__ sem, const float* __restrict__ ocr,
                                const int* __restrict__ mask,
                                const float* __restrict__ lnw, const float* __restrict__ lnb,
                                float* __restrict__ out)
{
    __shared__ float sh[4];
    int row = blockIdx.x;
    int tid = threadIdx.x;
    float* y = out + (size_t)row * DS;

    if (mask[row] == 0) {
        for (int i = tid; i < DS; i += 128)
            y[i] = MASKED_CNORM * lnw[i] + lnb[i];
        return;
    }

    const float* o = ocr + (size_t)row * DS;
    const float* s = sem + (size_t)row * DS;

    float x0 = o[tid]       + s[tid];
    float x1 = o[tid + 128] + s[tid + 128];
    float x2 = 0.f;
    float sum = x0 + x1;
    if (tid < 44) { x2 = o[tid + 256] + s[tid + 256]; sum += x2; }

#pragma unroll
    for (int oo = 16; oo > 0; oo >>= 1) sum += __shfl_xor_sync(0xffffffffu, sum, oo);
    if ((tid & 31) == 0) sh[tid >> 5] = sum;
    __syncthreads();
    sum = sh[0] + sh[1] + sh[2] + sh[3];
    __syncthreads();

    float mu = sum * (1.0f / 300.0f);
    float d0 = x0 - mu, d1 = x1 - mu, d2 = (tid < 44) ? (x2 - mu) : 0.f;
    float vs = d0 * d0 + d1 * d1 + d2 * d2;
#pragma unroll
    for (int oo = 16; oo > 0; oo >>= 1) vs += __shfl_xor_sync(0xffffffffu, vs, oo);
    if ((tid & 31) == 0) sh[tid >> 5] = vs;
    __syncthreads();
    vs = sh[0] + sh[1] + sh[2] + sh[3];

    float inv = rsqrtf(vs * (1.0f / 300.0f) + 1e-5f);
    y[tid]       = d0 * inv * lnw[tid]       + lnb[tid];
    y[tid + 128] = d1 * inv * lnw[tid + 128] + lnb[tid + 128];
    if (tid < 44)
        y[tid + 256] = d2 * inv * lnw[tid + 256] + lnb[tid + 256];
}

// ---------------------------------------------------------------------------
extern "C" void kernel_launch(void* const* d_in, const int* in_sizes, int n_in,
                              void* d_out, int out_size)
{
    const float* concepts = (const float*)d_in[0];
    const float* ocr      = (const float*)d_in[1];
    const int*   mask     = (const int*)d_in[2];
    const float* wq       = (const float*)d_in[3];
    const float* bq       = (const float*)d_in[4];
    const float* wk       = (const float*)d_in[5];
    const float* bk       = (const float*)d_in[6];
    const float* lnw      = (const float*)d_in[7];
    const float* lnb      = (const float*)d_in[8];
    float* out = (float*)d_out;

    // SMEM: MI=4 & K=304: 256*624 + 3*10240 = 190464 ; MI=2 & K=512: 128*1040 + 30720 = 163840
    const int SM4 = 256 * (DP * 2 + 16) + NSTAGE * B_TILE;   // 190464
    const int SM2 = 128 * (NS * 2 + 16) + NSTAGE * B_TILE;   // 163840
    cudaFuncSetAttribute(gemm_ar_kernel<4>, cudaFuncAttributeMaxDynamicSharedMemorySize, SM4);
    cudaFuncSetAttribute(gemm_ar_kernel<2>, cudaFuncAttributeMaxDynamicSharedMemorySize, SM2);

    __half *c_h, *o_h, *ct_h, *wqh, *wkh, *Qh, *Kh, *Ph;
    float *A, *S;
    cudaGetSymbolAddress((void**)&c_h, g_c_h);
    cudaGetSymbolAddress((void**)&o_h, g_o_h);
    cudaGetSymbolAddress((void**)&ct_h, g_ct_h);
    cudaGetSymbolAddress((void**)&wqh, g_wq_h);
    cudaGetSymbolAddress((void**)&wkh, g_wk_h);
    cudaGetSymbolAddress((void**)&Qh, g_Qh);
    cudaGetSymbolAddress((void**)&Kh, g_Kh);
    cudaGetSymbolAddress((void**)&Ph, g_Ph);
    cudaGetSymbolAddress((void**)&A, g_A);
    cudaGetSymbolAddress((void**)&S, g_S);

    // fp16 conversions (padded [.. x 304])
    {
        int t1 = BN_ROWS * (DP / 4);
        cvt_pad_kernel<<<(t1 + 255) / 256, 256>>>(concepts, c_h, BN_ROWS, DS, DP);
        cvt_pad_kernel<<<(t1 + 255) / 256, 256>>>(ocr,      o_h, BN_ROWS, DS, DP);
        int t2 = DS * (DP / 4);
        cvt_pad_kernel<<<(t2 + 255) / 256, 256>>>(wq, wqh, DS, DS, DP);
        cvt_pad_kernel<<<(t2 + 255) / 256, 256>>>(wk, wkh, DS, DS, DP);
        dim3 tg((DS + 31) / 32, NS / 32, BB);
        transpose_h_kernel<<<tg, dim3(32, 8)>>>(concepts, ct_h);
    }

    // Fused projections: z=0: Q = concepts@wq^T+bq ; z=1: K = ocr@wk^T+bk (fp16 out, ldc=304)
    // Note z also indexes B: pass sB=0 won't work since B differs (wq vs wk)…
    // so launch separately per weight but fused over z for A/bias/out is invalid.
    // Instead: two launches (B must match); keep fusion only of the A slab reuse.
    gemm_ar_kernel<4><<<dim3(BN_ROWS / 256, 1, 1), 256, SM4>>>(
        c_h, nullptr, wqh, bq, nullptr, nullptr, Qh, nullptr,
        BN_ROWS, DS, DP, DP, /*nTiles=*/3, 0, 0, 0, 1.0f);
    gemm_ar_kernel<4><<<dim3(BN_ROWS / 256, 1, 1), 256, SM4>>>(
        o_h, nullptr, wkh, bk, nullptr, nullptr, Kh, nullptr,
        BN_ROWS, DS, DP, DP, /*nTiles=*/3, 0, 0, 0, 1.0f);

    // scores[b] = (Q K^T)/sqrt(D)  fp32, grid y=2 halves of N=512, 2 inner n-tiles
    gemm_ar_kernel<4><<<dim3(NS / 256, 2, BB), 256, SM4>>>(
        Qh, nullptr, Kh, nullptr, nullptr, A, nullptr, nullptr,
        NS, NS, DP, NS, /*nTiles=*/2,
        (long long)NS * DP, (long long)NS * DP, (long long)NS * NS, INV_SQRT_D);

    // softmax -> P fp16
    softmax_h_kernel<<<BN_ROWS, 128>>>(A, Ph);

    // sem[b] = P @ concepts[b]  (B = concepts^T, K=512), MTILE=128, 3 inner n-tiles
    gemm_ar_kernel<2><<<dim3(NS / 128, 1, BB), 256, SM2>>>(
        Ph, nullptr, ct_h, nullptr, nullptr, S, nullptr, nullptr,
        NS, DS, NS, DS, /*nTiles=*/3,
        (long long)NS * NS, (long long)DS * NS, (long long)NS * DS, 1.0f);

    // mask + residual + LayerNorm
    epilogue_kernel<<<BN_ROWS, 128>>>(S, ocr, mask, lnw, lnb, out);

    (void)in_sizes; (void)n_in; (void)out_size;
}

// round 14
// speedup vs baseline: 3.8319x; 1.0744x over previous
#include <cuda_runtime.h>
#include <cuda_fp16.h>
#include <cstdint>

#define BB 64
#define NS 512
#define DS 300
#define DP 304                          // K padded to multiple of 16
#define BN_ROWS (BB*NS)                 // 32768
#define INV_SQRT_D 0.057735026918962576f
#define MASKED_CNORM (1.0f)

// ---------------------------------------------------------------------------
// Device-global scratch (runtime allocation forbidden); 16B-aligned rows.
// ---------------------------------------------------------------------------
__device__ alignas(1024) __half g_c_h[(size_t)BN_ROWS * DP];     // concepts fp16
__device__ alignas(1024) __half g_o_h[(size_t)BN_ROWS * DP];     // ocr fp16
__device__ alignas(1024) __half g_ct_h[(size_t)BB * DS * NS];    // concepts^T fp16
__device__ alignas(1024) __half g_wq_h[DS * DP];
__device__ alignas(1024) __half g_wk_h[DS * DP];
__device__ alignas(1024) __half g_Qh[(size_t)BN_ROWS * DP];
__device__ alignas(1024) __half g_Kh[(size_t)BN_ROWS * DP];
__device__ alignas(1024) __half g_Ph[(size_t)BB * NS * NS];
__device__ alignas(1024) float  g_A[(size_t)BB * NS * NS];       // scores fp32
__device__ alignas(1024) float  g_S[(size_t)BN_ROWS * DS];       // semantic fp32

// ---------------------------------------------------------------------------
// PTX helpers (sm_80-era only; compiles under compute_103)
// ---------------------------------------------------------------------------
__device__ __forceinline__ uint32_t smem_to_u32(const void* p) {
    uint32_t a;
    asm("{ .reg .u64 t; cvta.to.shared.u64 t, %1; cvt.u32.u64 %0, t; }" : "=r"(a) : "l"(p));
    return a;
}
__device__ __forceinline__ void cp_async16(uint32_t dst, const void* src) {
    asm volatile("cp.async.cg.shared.global [%0], [%1], 16;"
                 :: "r"(dst), "l"(src) : "memory");
}
#define CP_COMMIT() asm volatile("cp.async.commit_group;" ::: "memory")
#define CP_WAIT(n)  asm volatile("cp.async.wait_group %0;" :: "n"(n) : "memory")

__device__ __forceinline__ void ldsm_x4(uint32_t* r, uint32_t addr) {
    asm volatile("ldmatrix.sync.aligned.m8n8.x4.shared.b16 {%0,%1,%2,%3}, [%4];"
                 : "=r"(r[0]), "=r"(r[1]), "=r"(r[2]), "=r"(r[3]) : "r"(addr));
}
__device__ __forceinline__ void mma16816h(float* d, const uint32_t* a, const uint32_t* b) {
    asm volatile("mma.sync.aligned.m16n8k16.row.col.f32.f16.f16.f32 "
                 "{%0,%1,%2,%3}, {%4,%5,%6,%7}, {%8,%9}, {%0,%1,%2,%3};"
                 : "+f"(d[0]), "+f"(d[1]), "+f"(d[2]), "+f"(d[3])
                 : "r"(a[0]), "r"(a[1]), "r"(a[2]), "r"(a[3]), "r"(b[0]), "r"(b[1]));
}

// ---------------------------------------------------------------------------
// A-resident GEMM (NT): C[r,c] = scale * sum_k A[r,k]*B[c,k] (+bias[c]).
// A slab (MTILE x K fp16, row stride K*2+16 B) loaded to SMEM once; CTA loops
// nTiles n-tiles of 128 cols; per n-tile a 3-stage cp.async pipeline stages
// B chunks of 128 rows x 64 k (ROW 144 B; stride = 4 words mod 32 -> ldsm
// phases conflict-free). 256 threads, 8 warps (4m x 2n), MI m-frags/warp.
// Per-warp nCap trims n-columns to true N.
// Proj fusion: if Ah2 != null, blockIdx.z selects {A,B,bias,Cout} set.
// REQUIRES K%16==0, M%MTILE==0, 16B-aligned rows.
// ---------------------------------------------------------------------------
#define BROW_B  144                    // 128B data (64 halves) + 16B pad
#define B_TILE  (128 * BROW_B)         // 18432
#define NSTAGE  3

template<int MI>
__global__ void __launch_bounds__(256)
gemm_ar_kernel(const __half* __restrict__ Ah, const __half* __restrict__ Ah2,
               const __half* __restrict__ Bh, const __half* __restrict__ Bh2,
               const float* __restrict__ bias, const float* __restrict__ bias2,
               float* __restrict__ Cf, __half* __restrict__ Ch, __half* __restrict__ Ch2,
               int M, int N, int K, int ldc, int nTiles,
               long long sA, long long sB, long long sC, float scale)
{
    constexpr int MTILE = MI * 64;
    extern __shared__ __align__(128) char smem[];
    uint32_t smem_base = smem_to_u32(smem);
    int tid = threadIdx.x;
    int wid = tid >> 5, lane = tid & 31;
    int wm = wid & 3, wn = wid >> 2;
    int z = blockIdx.z;
    int rowBase = blockIdx.x * MTILE;
    int colBase0 = blockIdx.y * (nTiles * 128);

    const int strideA = K * 2 + 16;                 // bytes, %16==0
    const uint32_t aSize = (uint32_t)MTILE * strideA;
    const int segsPerRow = K >> 3;

    const __half* pA;
    const __half* pB;
    const float* pb;
    float* pCf;
    __half* pCh;
    if (Ah2) {                                      // fused operand-set select
        pA  = z ? Ah2 : Ah;
        pB  = z ? Bh2 : Bh;
        pb  = z ? bias2 : bias;
        pCh = z ? Ch2 : Ch;
        pCf = nullptr;
    } else {
        pA  = Ah + (size_t)z * sA;
        pB  = Bh + (size_t)z * sB;
        pb  = bias;
        pCf = Cf ? Cf + (size_t)z * sC : nullptr;
        pCh = Ch ? Ch + (size_t)z * sC : nullptr;
    }

    // ---- Load A slab into SMEM (one group) ----
    {
        int total = MTILE * segsPerRow;
        for (int s = tid; s < total; s += 256) {
            int r = s / segsPerRow, cs = s - r * segsPerRow;
            cp_async16(smem_base + (uint32_t)r * strideA + cs * 16,
                       pA + (size_t)(rowBase + r) * K + cs * 8);
        }
        CP_COMMIT();
    }

    int nChunks = (K + 63) >> 6;

    auto prefB = [&](int c, int stage, int colBase) {
        int k0 = c << 6;
        int ksegs = (K - k0) >> 3;                 // up to 8
        if (ksegs > 8) ksegs = 8;
        uint32_t sb = smem_base + aSize + stage * B_TILE;
#pragma unroll
        for (int i = 0; i < 4; i++) {
            int s = tid + i * 256;                 // 0..1023: 128 rows x 8 segs
            int r = s >> 3, cs = s & 7;
            int bRow = colBase + r;
            if (bRow < N && cs < ksegs)
                cp_async16(sb + r * BROW_B + cs * 16,
                           pB + (size_t)bRow * K + k0 + cs * 8);
        }
    };

#pragma unroll 1
    for (int nt = 0; nt < nTiles; nt++) {
        int colBase = colBase0 + nt * 128;
        int rem = N - colBase - wn * 64;
        int nCap = rem >= 64 ? 8 : (rem <= 0 ? 0 : ((rem + 7) >> 3));

        float acc[MI][8][4];
#pragma unroll
        for (int mi = 0; mi < MI; mi++)
#pragma unroll
            for (int ni = 0; ni < 8; ni++)
#pragma unroll
                for (int j = 0; j < 4; j++) acc[mi][ni][j] = 0.f;

        prefB(0, 0, colBase); CP_COMMIT();
        if (nChunks > 1) prefB(1, 1, colBase);
        CP_COMMIT();

#pragma unroll 1
        for (int c = 0; c < nChunks; c++) {
            int st = c % 3;
            if (c + 2 < nChunks) prefB(c + 2, (c + 2) % 3, colBase);
            CP_COMMIT();
            CP_WAIT(2);
            __syncthreads();

            int ksMax = (K - (c << 6)) >> 4;       // up to 4
            if (ksMax > 4) ksMax = 4;
            uint32_t sbB = smem_base + aSize + st * B_TILE;
#pragma unroll 1
            for (int ks = 0; ks < ksMax; ks++) {
                int kstep = c * 4 + ks;
                uint32_t ah[MI][4], bcur[8][2];
#pragma unroll
                for (int mi = 0; mi < MI; mi++) {
                    uint32_t addr = smem_base +
                        (uint32_t)((wm * (MI * 16) + mi * 16 + (lane & 15)) * strideA)
                        + ((lane >> 4) * 16) + kstep * 32;
                    ldsm_x4(ah[mi], addr);
                }
#pragma unroll
                for (int g = 0; g < 4; g++) {
                    if (g * 2 < nCap) {
                        int j = lane & 7, grp = lane >> 3;
                        uint32_t addr = sbB +
                            (uint32_t)((wn * 64 + g * 16 + ((grp >> 1) * 8) + j) * BROW_B
                                       + ((grp & 1) * 16) + ks * 32);
                        uint32_t r[4];
                        ldsm_x4(r, addr);
                        bcur[2*g][0] = r[0]; bcur[2*g][1] = r[1];
                        bcur[2*g+1][0] = r[2]; bcur[2*g+1][1] = r[3];
                    }
                }
#pragma unroll
                for (int mi = 0; mi < MI; mi++)
#pragma unroll
                    for (int ni = 0; ni < 8; ni++)
                        if (ni < nCap) mma16816h(acc[mi][ni], ah[mi], bcur[ni]);
            }
            __syncthreads();
        }

        // Epilogue for this n-tile
#pragma unroll
        for (int mi = 0; mi < MI; mi++) {
#pragma unroll
            for (int ni = 0; ni < 8; ni++) {
#pragma unroll
                for (int half = 0; half < 2; half++) {
                    int gm = rowBase + wm * (MI * 16) + mi * 16 + (lane >> 2) + half * 8;
                    int gn = colBase + wn * 64 + ni * 8 + 2 * (lane & 3);
                    if (gn >= ldc) continue;
                    size_t o = (size_t)gm * ldc + gn;
                    if (gn < N) {
                        float v0 = acc[mi][ni][2*half]   * scale;
                        float v1 = acc[mi][ni][2*half+1] * scale;
                        if (pb) { v0 += pb[gn]; v1 += (gn + 1 < N) ? pb[gn+1] : 0.f; }
                        bool ok1 = (gn + 1 < N);
                        if (pCf) {
                            pCf[o] = v0;
                            if (ok1) pCf[o+1] = v1;
                        }
                        if (pCh) {
                            pCh[o] = __float2half(v0);
                            if (ok1) pCh[o+1] = __float2half(v1);
                            else if (gn + 1 < ldc) pCh[o+1] = __float2half(0.f);
                        }
                    } else if (pCh) {
                        pCh[o] = __float2half(0.f);
                        if (gn + 1 < ldc) pCh[o+1] = __float2half(0.f);
                    }
                }
            }
        }
        CP_WAIT(0);
        __syncthreads();
    }
}

// ---------------------------------------------------------------------------
// Fused pair conversion: fp32 [rows x kin] -> fp16 [rows x kout], pad zero.
// blockIdx.y selects (x0->h0) or (x1->h1).
// ---------------------------------------------------------------------------
__global__ void cvt_pad2_kernel(const float* __restrict__ x0, const float* __restrict__ x1,
                                __half* __restrict__ h0, __half* __restrict__ h1,
                                int rows, int kin, int kout)
{
    const float* x = blockIdx.y ? x1 : x0;
    __half* h = blockIdx.y ? h1 : h0;
    int q = kout >> 2;
    int i4 = blockIdx.x * blockDim.x + threadIdx.x;
    if (i4 >= rows * q) return;
    int r = i4 / q, c = (i4 - r * q) << 2;
    __half hv[4];
    if (c < kin) {
        float4 v = *(const float4*)(x + (size_t)r * kin + c);
        hv[0] = __float2half(v.x); hv[1] = __float2half(v.y);
        hv[2] = __float2half(v.z); hv[3] = __float2half(v.w);
    } else {
        __half zz = __float2half(0.f);
        hv[0]=hv[1]=hv[2]=hv[3]=zz;
    }
    size_t o = (size_t)r * kout + c;
    h[o]=hv[0]; h[o+1]=hv[1]; h[o+2]=hv[2]; h[o+3]=hv[3];
}

// concepts [b][m][300] -> ct [b][d][512] fp16
__global__ void transpose_h_kernel(const float* __restrict__ in, __half* __restrict__ oh)
{
    __shared__ float t[32][33];
    int b = blockIdx.z;
    int dBase = blockIdx.x * 32, mBase = blockIdx.y * 32;
    int tx = threadIdx.x, ty = threadIdx.y;
#pragma unroll
    for (int i = 0; i < 4; i++) {
        int m = mBase + ty + i * 8, d = dBase + tx;
        if (d < DS) t[ty + i * 8][tx] = in[((size_t)b * NS + m) * DS + d];
    }
    __syncthreads();
#pragma unroll
    for (int i = 0; i < 4; i++) {
        int d = dBase + ty + i * 8, m = mBase + tx;
        if (d < DS)
            oh[((size_t)b * DS + d) * NS + m] = __float2half(t[tx][ty + i * 8]);
    }
}

// ---------------------------------------------------------------------------
// Row softmax over N=512, output fp16 probs
// ---------------------------------------------------------------------------
__global__ void softmax_h_kernel(const float* __restrict__ A, __half* __restrict__ Ph)
{
    __shared__ float sh[4];
    int row = blockIdx.x;
    const float* a = A + (size_t)row * NS;
    int tid = threadIdx.x;

    float v0 = a[tid], v1 = a[tid + 128], v2 = a[tid + 256], v3 = a[tid + 384];
    float mx = fmaxf(fmaxf(v0, v1), fmaxf(v2, v3));
#pragma unroll
    for (int o = 16; o > 0; o >>= 1) mx = fmaxf(mx, __shfl_xor_sync(0xffffffffu, mx, o));
    if ((tid & 31) == 0) sh[tid >> 5] = mx;
    __syncthreads();
    mx = fmaxf(fmaxf(sh[0], sh[1]), fmaxf(sh[2], sh[3]));
    __syncthreads();

    v0 = expf(v0 - mx); v1 = expf(v1 - mx); v2 = expf(v2 - mx); v3 = expf(v3 - mx);
    float s = v0 + v1 + v2 + v3;
#pragma unroll
    for (int o = 16; o > 0; o >>= 1) s += __shfl_xor_sync(0xffffffffu, s, o);
    if ((tid & 31) == 0) sh[tid >> 5] = s;
    __syncthreads();
    s = sh[0] + sh[1] + sh[2] + sh[3];

    float inv = 1.0f / s;
    size_t base = (size_t)row * NS;
    Ph[base + tid]       = __float2half(v0 * inv);
    Ph[base + tid + 128] = __float2half(v1 * inv);
    Ph[base + tid + 256] = __float2half(v2 * inv);
    Ph[base + tid + 384] = __float2half(v3 * inv);
}

// ---------------------------------------------------------------------------
// Mask fill + residual + LayerNorm (verified since R2)
// ---------------------------------------------------------------------------
__global__ void epilogue_kernel(const float* __restrict__ sem, const float* __restrict__ ocr,
                                const int* __restrict__ mask,
                                const float* __restrict__ lnw, const float* __restrict__ lnb,
                                float* __restrict__ out)
{
    __shared__ float sh[4];
    int row = blockIdx.x;
    int tid = threadIdx.x;
    float* y = out + (size_t)row * DS;

    if (mask[row] == 0) {
        for (int i = tid; i < DS; i += 128)
            y[i] = MASKED_CNORM * lnw[i] + lnb[i];
        return;
    }

    const float* o = ocr + (size_t)row * DS;
    const float* s = sem + (size_t)row * DS;

    float x0 = o[tid]       + s[tid];
    float x1 = o[tid + 128] + s[tid + 128];
    float x2 = 0.f;
    float sum = x0 + x1;
    if (tid < 44) { x2 = o[tid + 256] + s[tid + 256]; sum += x2; }

#pragma unroll
    for (int oo = 16; oo > 0; oo >>= 1) sum += __shfl_xor_sync(0xffffffffu, sum, oo);
    if ((tid & 31) == 0) sh[tid >> 5] = sum;
    __syncthreads();
    sum = sh[0] + sh[1] + sh[2] + sh[3];
    __syncthreads();

    float mu = sum * (1.0f / 300.0f);
    float d0 = x0 - mu, d1 = x1 - mu, d2 = (tid < 44) ? (x2 - mu) : 0.f;
    float vs = d0 * d0 + d1 * d1 + d2 * d2;
#pragma unroll
    for (int oo = 16; oo > 0; oo >>= 1) vs += __shfl_xor_sync(0xffffffffu, vs, oo);
    if ((tid & 31) == 0) sh[tid >> 5] = vs;
    __syncthreads();
    vs = sh[0] + sh[1] + sh[2] + sh[3];

    float inv = rsqrtf(vs * (1.0f / 300.0f) + 1e-5f);
    y[tid]       = d0 * inv * lnw[tid]       + lnb[tid];
    y[tid + 128] = d1 * inv * lnw[tid + 128] + lnb[tid + 128];
    if (tid < 44)
        y[tid + 256] = d2 * inv * lnw[tid + 256] + lnb[tid + 256];
}

// ---------------------------------------------------------------------------
extern "C" void kernel_launch(void* const* d_in, const int* in_sizes, int n_in,
                              void* d_out, int out_size)
{
    const float* concepts = (const float*)d_in[0];
    const float* ocr      = (const float*)d_in[1];
    const int*   mask     = (const int*)d_in[2];
    const float* wq       = (const float*)d_in[3];
    const float* bq       = (const float*)d_in[4];
    const float* wk       = (const float*)d_in[5];
    const float* bk       = (const float*)d_in[6];
    const float* lnw      = (const float*)d_in[7];
    const float* lnb      = (const float*)d_in[8];
    float* out = (float*)d_out;

    // SMEM: MI=4 & K=304: 256*624 + 3*18432 = 215040 ; MI=2 & K=512: 128*1040 + 55296 = 188416
    const int SM4 = 256 * (DP * 2 + 16) + NSTAGE * B_TILE;
    const int SM2 = 128 * (NS * 2 + 16) + NSTAGE * B_TILE;
    cudaFuncSetAttribute(gemm_ar_kernel<4>, cudaFuncAttributeMaxDynamicSharedMemorySize, SM4);
    cudaFuncSetAttribute(gemm_ar_kernel<2>, cudaFuncAttributeMaxDynamicSharedMemorySize, SM2);

    __half *c_h, *o_h, *ct_h, *wqh, *wkh, *Qh, *Kh, *Ph;
    float *A, *S;
    cudaGetSymbolAddress((void**)&c_h, g_c_h);
    cudaGetSymbolAddress((void**)&o_h, g_o_h);
    cudaGetSymbolAddress((void**)&ct_h, g_ct_h);
    cudaGetSymbolAddress((void**)&wqh, g_wq_h);
    cudaGetSymbolAddress((void**)&wkh, g_wk_h);
    cudaGetSymbolAddress((void**)&Qh, g_Qh);
    cudaGetSymbolAddress((void**)&Kh, g_Kh);
    cudaGetSymbolAddress((void**)&Ph, g_Ph);
    cudaGetSymbolAddress((void**)&A, g_A);
    cudaGetSymbolAddress((void**)&S, g_S);

    // fp16 conversions (padded [.. x 304]); fused pairs via grid.y
    {
        int t1 = BN_ROWS * (DP / 4);
        cvt_pad2_kernel<<<dim3((t1 + 255) / 256, 2), 256>>>(
            concepts, ocr, c_h, o_h, BN_ROWS, DS, DP);
        int t2 = DS * (DP / 4);
        cvt_pad2_kernel<<<dim3((t2 + 255) / 256, 2), 256>>>(
            wq, wk, wqh, wkh, DS, DS, DP);
        dim3 tg((DS + 31) / 32, NS / 32, BB);
        transpose_h_kernel<<<tg, dim3(32, 8)>>>(concepts, ct_h);
    }

    // Fused projections: z=0: Q = concepts@wq^T+bq ; z=1: K = ocr@wk^T+bk (fp16, ldc=304)
    gemm_ar_kernel<4><<<dim3(BN_ROWS / 256, 1, 2), 256, SM4>>>(
        c_h, o_h, wqh, wkh, bq, bk, nullptr, Qh, Kh,
        BN_ROWS, DS, DP, DP, /*nTiles=*/3, 0, 0, 0, 1.0f);

    // scores[b] = (Q K^T)/sqrt(D)  fp32, one CTA covers full N via 4 inner n-tiles
    gemm_ar_kernel<4><<<dim3(NS / 256, 1, BB), 256, SM4>>>(
        Qh, nullptr, Kh, nullptr, nullptr, nullptr, A, nullptr, nullptr,
        NS, NS, DP, NS, /*nTiles=*/4,
        (long long)NS * DP, (long long)NS * DP, (long long)NS * NS, INV_SQRT_D);

    // softmax -> P fp16
    softmax_h_kernel<<<BN_ROWS, 128>>>(A, Ph);

    // sem[b] = P @ concepts[b]  (B = concepts^T, K=512), MTILE=128, 3 inner n-tiles
    gemm_ar_kernel<2><<<dim3(NS / 128, 1, BB), 256, SM2>>>(
        Ph, nullptr, ct_h, nullptr, nullptr, nullptr, S, nullptr, nullptr,
        NS, DS, NS, DS, /*nTiles=*/3,
        (long long)NS * NS, (long long)DS * NS, (long long)NS * DS, 1.0f);

    // mask + residual + LayerNorm
    epilogue_kernel<<<BN_ROWS, 128>>>(S, ocr, mask, lnw, lnb, out);

    (void)in_sizes; (void)n_in; (void)out_size;
}

// round 15
// speedup vs baseline: 3.9754x; 1.0374x over previous
#include <cuda_runtime.h>
#include <cuda_fp16.h>
#include <cstdint>

#define BB 64
#define NS 512
#define DS 300
#define DP 304                          // K padded to multiple of 16
#define BN_ROWS (BB*NS)                 // 32768
#define INV_SQRT_D 0.057735026918962576f
#define MASKED_CNORM (1.0f)

// ---------------------------------------------------------------------------
// Device-global scratch (runtime allocation forbidden); 16B-aligned rows.
// ---------------------------------------------------------------------------
__device__ alignas(1024) __half g_c_h[(size_t)BN_ROWS * DP];     // concepts fp16
__device__ alignas(1024) __half g_o_h[(size_t)BN_ROWS * DP];     // ocr fp16
__device__ alignas(1024) __half g_ct_h[(size_t)BB * DS * NS];    // concepts^T fp16
__device__ alignas(1024) __half g_wq_h[DS * DP];
__device__ alignas(1024) __half g_wk_h[DS * DP];
__device__ alignas(1024) __half g_Qh[(size_t)BN_ROWS * DP];
__device__ alignas(1024) __half g_Kh[(size_t)BN_ROWS * DP];
__device__ alignas(1024) __half g_Ph[(size_t)BB * NS * NS];
__device__ alignas(1024) float  g_A[(size_t)BB * NS * NS];       // scores fp32
__device__ alignas(1024) float  g_S[(size_t)BN_ROWS * DS];       // semantic fp32

// ---------------------------------------------------------------------------
// PTX helpers (sm_80-era only; compiles under compute_103)
// ---------------------------------------------------------------------------
__device__ __forceinline__ uint32_t smem_to_u32(const void* p) {
    uint32_t a;
    asm("{ .reg .u64 t; cvta.to.shared.u64 t, %1; cvt.u32.u64 %0, t; }" : "=r"(a) : "l"(p));
    return a;
}
__device__ __forceinline__ void cp_async16(uint32_t dst, const void* src) {
    asm volatile("cp.async.cg.shared.global [%0], [%1], 16;"
                 :: "r"(dst), "l"(src) : "memory");
}
#define CP_COMMIT() asm volatile("cp.async.commit_group;" ::: "memory")
#define CP_WAIT(n)  asm volatile("cp.async.wait_group %0;" :: "n"(n) : "memory")

__device__ __forceinline__ void ldsm_x4(uint32_t* r, uint32_t addr) {
    asm volatile("ldmatrix.sync.aligned.m8n8.x4.shared.b16 {%0,%1,%2,%3}, [%4];"
                 : "=r"(r[0]), "=r"(r[1]), "=r"(r[2]), "=r"(r[3]) : "r"(addr));
}
__device__ __forceinline__ void mma16816h(float* d, const uint32_t* a, const uint32_t* b) {
    asm volatile("mma.sync.aligned.m16n8k16.row.col.f32.f16.f16.f32 "
                 "{%0,%1,%2,%3}, {%4,%5,%6,%7}, {%8,%9}, {%0,%1,%2,%3};"
                 : "+f"(d[0]), "+f"(d[1]), "+f"(d[2]), "+f"(d[3])
                 : "r"(a[0]), "r"(a[1]), "r"(a[2]), "r"(a[3]), "r"(b[0]), "r"(b[1]));
}

// ---------------------------------------------------------------------------
// A-resident GEMM (NT): C[r,c] = scale * sum_k A[r,k]*B[c,k] (+bias[c]).
// A slab (MTILE x K fp16, row stride K*2+16 B) in SMEM once; CTA loops nTiles
// n-tiles of 128 cols; 3-stage cp.async pipeline stages B chunks 128 x 64k
// (row 144 B, ldsm conflict-free). 512 threads, 16 warps (4m x 4n) — doubles
// per-SMSP eligible warps vs R14 to cover ldsm->mma latency. Warp tile
// (MI*16) x 32. Per-warp nCap trims n-columns to true N.
// Proj fusion: if Ah2 != null, blockIdx.z selects {A,B,bias,Cout} set.
// REQUIRES K%16==0, M%MTILE==0, 16B-aligned rows.
// ---------------------------------------------------------------------------
#define BROW_B  144                    // 128B data (64 halves) + 16B pad
#define B_TILE  (128 * BROW_B)         // 18432
#define NSTAGE  3

template<int MI>
__global__ void __launch_bounds__(512)
gemm_ar_kernel(const __half* __restrict__ Ah, const __half* __restrict__ Ah2,
               const __half* __restrict__ Bh, const __half* __restrict__ Bh2,
               const float* __restrict__ bias, const float* __restrict__ bias2,
               float* __restrict__ Cf, __half* __restrict__ Ch, __half* __restrict__ Ch2,
               int M, int N, int K, int ldc, int nTiles,
               long long sA, long long sB, long long sC, float scale)
{
    constexpr int MTILE = MI * 64;
    extern __shared__ __align__(128) char smem[];
    uint32_t smem_base = smem_to_u32(smem);
    int tid = threadIdx.x;
    int wid = tid >> 5, lane = tid & 31;
    int wm = wid & 3, wn = wid >> 2;              // 4m x 4n
    int z = blockIdx.z;
    int rowBase = blockIdx.x * MTILE;
    int colBase0 = blockIdx.y * (nTiles * 128);

    const int strideA = K * 2 + 16;               // bytes, %16==0
    const uint32_t aSize = (uint32_t)MTILE * strideA;
    const int segsPerRow = K >> 3;

    const __half* pA;
    const __half* pB;
    const float* pb;
    float* pCf;
    __half* pCh;
    if (Ah2) {                                    // fused operand-set select
        pA  = z ? Ah2 : Ah;
        pB  = z ? Bh2 : Bh;
        pb  = z ? bias2 : bias;
        pCh = z ? Ch2 : Ch;
        pCf = nullptr;
    } else {
        pA  = Ah + (size_t)z * sA;
        pB  = Bh + (size_t)z * sB;
        pb  = bias;
        pCf = Cf ? Cf + (size_t)z * sC : nullptr;
        pCh = Ch ? Ch + (size_t)z * sC : nullptr;
    }

    // ---- Load A slab into SMEM (one group) ----
    {
        int total = MTILE * segsPerRow;
        for (int s = tid; s < total; s += 512) {
            int r = s / segsPerRow, cs = s - r * segsPerRow;
            cp_async16(smem_base + (uint32_t)r * strideA + cs * 16,
                       pA + (size_t)(rowBase + r) * K + cs * 8);
        }
        CP_COMMIT();
    }

    int nChunks = (K + 63) >> 6;

    auto prefB = [&](int c, int stage, int colBase) {
        int k0 = c << 6;
        int ksegs = (K - k0) >> 3;                // up to 8
        if (ksegs > 8) ksegs = 8;
        uint32_t sb = smem_base + aSize + stage * B_TILE;
#pragma unroll
        for (int i = 0; i < 2; i++) {
            int s = tid + i * 512;                // 0..1023: 128 rows x 8 segs
            int r = s >> 3, cs = s & 7;
            int bRow = colBase + r;
            if (bRow < N && cs < ksegs)
                cp_async16(sb + r * BROW_B + cs * 16,
                           pB + (size_t)bRow * K + k0 + cs * 8);
        }
    };

#pragma unroll 1
    for (int nt = 0; nt < nTiles; nt++) {
        int colBase = colBase0 + nt * 128;
        int rem = N - colBase - wn * 32;
        int nCap = rem >= 32 ? 4 : (rem <= 0 ? 0 : ((rem + 7) >> 3));

        float acc[MI][4][4];
#pragma unroll
        for (int mi = 0; mi < MI; mi++)
#pragma unroll
            for (int ni = 0; ni < 4; ni++)
#pragma unroll
                for (int j = 0; j < 4; j++) acc[mi][ni][j] = 0.f;

        prefB(0, 0, colBase); CP_COMMIT();
        if (nChunks > 1) prefB(1, 1, colBase);
        CP_COMMIT();

#pragma unroll 1
        for (int c = 0; c < nChunks; c++) {
            int st = c % 3;
            if (c + 2 < nChunks) prefB(c + 2, (c + 2) % 3, colBase);
            CP_COMMIT();
            CP_WAIT(2);
            __syncthreads();

            int ksMax = (K - (c << 6)) >> 4;      // up to 4
            if (ksMax > 4) ksMax = 4;
            uint32_t sbB = smem_base + aSize + st * B_TILE;
#pragma unroll 1
            for (int ks = 0; ks < ksMax; ks++) {
                int kstep = c * 4 + ks;
                uint32_t ah[MI][4], bcur[4][2];
#pragma unroll
                for (int mi = 0; mi < MI; mi++) {
                    uint32_t addr = smem_base +
                        (uint32_t)((wm * (MI * 16) + mi * 16 + (lane & 15)) * strideA)
                        + ((lane >> 4) * 16) + kstep * 32;
                    ldsm_x4(ah[mi], addr);
                }
#pragma unroll
                for (int g = 0; g < 2; g++) {
                    if (g * 2 < nCap) {
                        int j = lane & 7, grp = lane >> 3;
                        uint32_t addr = sbB +
                            (uint32_t)((wn * 32 + g * 16 + ((grp >> 1) * 8) + j) * BROW_B
                                       + ((grp & 1) * 16) + ks * 32);
                        uint32_t r[4];
                        ldsm_x4(r, addr);
                        bcur[2*g][0] = r[0]; bcur[2*g][1] = r[1];
                        bcur[2*g+1][0] = r[2]; bcur[2*g+1][1] = r[3];
                    }
                }
#pragma unroll
                for (int mi = 0; mi < MI; mi++)
#pragma unroll
                    for (int ni = 0; ni < 4; ni++)
                        if (ni < nCap) mma16816h(acc[mi][ni], ah[mi], bcur[ni]);
            }
            __syncthreads();
        }

        // Epilogue for this n-tile
#pragma unroll
        for (int mi = 0; mi < MI; mi++) {
#pragma unroll
            for (int ni = 0; ni < 4; ni++) {
#pragma unroll
                for (int half = 0; half < 2; half++) {
                    int gm = rowBase + wm * (MI * 16) + mi * 16 + (lane >> 2) + half * 8;
                    int gn = colBase + wn * 32 + ni * 8 + 2 * (lane & 3);
                    if (gn >= ldc) continue;
                    size_t o = (size_t)gm * ldc + gn;
                    if (gn < N) {
                        float v0 = acc[mi][ni][2*half]   * scale;
                        float v1 = acc[mi][ni][2*half+1] * scale;
                        if (pb) { v0 += pb[gn]; v1 += (gn + 1 < N) ? pb[gn+1] : 0.f; }
                        bool ok1 = (gn + 1 < N);
                        if (pCf) {
                            pCf[o] = v0;
                            if (ok1) pCf[o+1] = v1;
                        }
                        if (pCh) {
                            pCh[o] = __float2half(v0);
                            if (ok1) pCh[o+1] = __float2half(v1);
                            else if (gn + 1 < ldc) pCh[o+1] = __float2half(0.f);
                        }
                    } else if (pCh) {
                        pCh[o] = __float2half(0.f);
                        if (gn + 1 < ldc) pCh[o+1] = __float2half(0.f);
                    }
                }
            }
        }
        CP_WAIT(0);
        __syncthreads();
    }
}

// ---------------------------------------------------------------------------
// Fused pair conversion: fp32 [rows x kin] -> fp16 [rows x kout], pad zero.
// ---------------------------------------------------------------------------
__global__ void cvt_pad2_kernel(const float* __restrict__ x0, const float* __restrict__ x1,
                                __half* __restrict__ h0, __half* __restrict__ h1,
                                int rows, int kin, int kout)
{
    const float* x = blockIdx.y ? x1 : x0;
    __half* h = blockIdx.y ? h1 : h0;
    int q = kout >> 2;
    int i4 = blockIdx.x * blockDim.x + threadIdx.x;
    if (i4 >= rows * q) return;
    int r = i4 / q, c = (i4 - r * q) << 2;
    __half hv[4];
    if (c < kin) {
        float4 v = *(const float4*)(x + (size_t)r * kin + c);
        hv[0] = __float2half(v.x); hv[1] = __float2half(v.y);
        hv[2] = __float2half(v.z); hv[3] = __float2half(v.w);
    } else {
        __half zz = __float2half(0.f);
        hv[0]=hv[1]=hv[2]=hv[3]=zz;
    }
    size_t o = (size_t)r * kout + c;
    h[o]=hv[0]; h[o+1]=hv[1]; h[o+2]=hv[2]; h[o+3]=hv[3];
}

// concepts [b][m][300] -> ct [b][d][512] fp16
__global__ void transpose_h_kernel(const float* __restrict__ in, __half* __restrict__ oh)
{
    __shared__ float t[32][33];
    int b = blockIdx.z;
    int dBase = blockIdx.x * 32, mBase = blockIdx.y * 32;
    int tx = threadIdx.x, ty = threadIdx.y;
#pragma unroll
    for (int i = 0; i < 4; i++) {
        int m = mBase + ty + i * 8, d = dBase + tx;
        if (d < DS) t[ty + i * 8][tx] = in[((size_t)b * NS + m) * DS + d];
    }
    __syncthreads();
#pragma unroll
    for (int i = 0; i < 4; i++) {
        int d = dBase + ty + i * 8, m = mBase + tx;
        if (d < DS)
            oh[((size_t)b * DS + d) * NS + m] = __float2half(t[tx][ty + i * 8]);
    }
}

// ---------------------------------------------------------------------------
// Row softmax over N=512, output fp16 probs
// ---------------------------------------------------------------------------
__global__ void softmax_h_kernel(const float* __restrict__ A, __half* __restrict__ Ph)
{
    __shared__ float sh[4];
    int row = blockIdx.x;
    const float* a = A + (size_t)row * NS;
    int tid = threadIdx.x;

    float v0 = a[tid], v1 = a[tid + 128], v2 = a[tid + 256], v3 = a[tid + 384];
    float mx = fmaxf(fmaxf(v0, v1), fmaxf(v2, v3));
#pragma unroll
    for (int o = 16; o > 0; o >>= 1) mx = fmaxf(mx, __shfl_xor_sync(0xffffffffu, mx, o));
    if ((tid & 31) == 0) sh[tid >> 5] = mx;
    __syncthreads();
    mx = fmaxf(fmaxf(sh[0], sh[1]), fmaxf(sh[2], sh[3]));
    __syncthreads();

    v0 = expf(v0 - mx); v1 = expf(v1 - mx); v2 = expf(v2 - mx); v3 = expf(v3 - mx);
    float s = v0 + v1 + v2 + v3;
#pragma unroll
    for (int o = 16; o > 0; o >>= 1) s += __shfl_xor_sync(0xffffffffu, s, o);
    if ((tid & 31) == 0) sh[tid >> 5] = s;
    __syncthreads();
    s = sh[0] + sh[1] + sh[2] + sh[3];

    float inv = 1.0f / s;
    size_t base = (size_t)row * NS;
    Ph[base + tid]       = __float2half(v0 * inv);
    Ph[base + tid + 128] = __float2half(v1 * inv);
    Ph[base + tid + 256] = __float2half(v2 * inv);
    Ph[base + tid + 384] = __float2half(v3 * inv);
}

// ---------------------------------------------------------------------------
// Mask fill + residual + LayerNorm (verified since R2)
// ---------------------------------------------------------------------------
__global__ void epilogue_kernel(const float* __restrict__ sem, const float* __restrict__ ocr,
                                const int* __restrict__ mask,
                                const float* __restrict__ lnw, const float* __restrict__ lnb,
                                float* __restrict__ out)
{
    __shared__ float sh[4];
    int row = blockIdx.x;
    int tid = threadIdx.x;
    float* y = out + (size_t)row * DS;

    if (mask[row] == 0) {
        for (int i = tid; i < DS; i += 128)
            y[i] = MASKED_CNORM * lnw[i] + lnb[i];
        return;
    }

    const float* o = ocr + (size_t)row * DS;
    const float* s = sem + (size_t)row * DS;

    float x0 = o[tid]       + s[tid];
    float x1 = o[tid + 128] + s[tid + 128];
    float x2 = 0.f;
    float sum = x0 + x1;
    if (tid < 44) { x2 = o[tid + 256] + s[tid + 256]; sum += x2; }

#pragma unroll
    for (int oo = 16; oo > 0; oo >>= 1) sum += __shfl_xor_sync(0xffffffffu, sum, oo);
    if ((tid & 31) == 0) sh[tid >> 5] = sum;
    __syncthreads();
    sum = sh[0] + sh[1] + sh[2] + sh[3];
    __syncthreads();

    float mu = sum * (1.0f / 300.0f);
    float d0 = x0 - mu, d1 = x1 - mu, d2 = (tid < 44) ? (x2 - mu) : 0.f;
    float vs = d0 * d0 + d1 * d1 + d2 * d2;
#pragma unroll
    for (int oo = 16; oo > 0; oo >>= 1) vs += __shfl_xor_sync(0xffffffffu, vs, oo);
    if ((tid & 31) == 0) sh[tid >> 5] = vs;
    __syncthreads();
    vs = sh[0] + sh[1] + sh[2] + sh[3];

    float inv = rsqrtf(vs * (1.0f / 300.0f) + 1e-5f);
    y[tid]       = d0 * inv * lnw[tid]       + lnb[tid];
    y[tid + 128] = d1 * inv * lnw[tid + 128] + lnb[tid + 128];
    if (tid < 44)
        y[tid + 256] = d2 * inv * lnw[tid + 256] + lnb[tid + 256];
}

// ---------------------------------------------------------------------------
extern "C" void kernel_launch(void* const* d_in, const int* in_sizes, int n_in,
                              void* d_out, int out_size)
{
    const float* concepts = (const float*)d_in[0];
    const float* ocr      = (const float*)d_in[1];
    const int*   mask     = (const int*)d_in[2];
    const float* wq       = (const float*)d_in[3];
    const float* bq       = (const float*)d_in[4];
    const float* wk       = (const float*)d_in[5];
    const float* bk       = (const float*)d_in[6];
    const float* lnw      = (const float*)d_in[7];
    const float* lnb      = (const float*)d_in[8];
    float* out = (float*)d_out;

    // SMEM: MI=4 & K=304: 256*624 + 3*18432 = 215040 ; MI=2 & K=512: 128*1040 + 55296 = 188416
    const int SM4 = 256 * (DP * 2 + 16) + NSTAGE * B_TILE;
    const int SM2 = 128 * (NS * 2 + 16) + NSTAGE * B_TILE;
    cudaFuncSetAttribute(gemm_ar_kernel<4>, cudaFuncAttributeMaxDynamicSharedMemorySize, SM4);
    cudaFuncSetAttribute(gemm_ar_kernel<2>, cudaFuncAttributeMaxDynamicSharedMemorySize, SM2);

    __half *c_h, *o_h, *ct_h, *wqh, *wkh, *Qh, *Kh, *Ph;
    float *A, *S;
    cudaGetSymbolAddress((void**)&c_h, g_c_h);
    cudaGetSymbolAddress((void**)&o_h, g_o_h);
    cudaGetSymbolAddress((void**)&ct_h, g_ct_h);
    cudaGetSymbolAddress((void**)&wqh, g_wq_h);
    cudaGetSymbolAddress((void**)&wkh, g_wk_h);
    cudaGetSymbolAddress((void**)&Qh, g_Qh);
    cudaGetSymbolAddress((void**)&Kh, g_Kh);
    cudaGetSymbolAddress((void**)&Ph, g_Ph);
    cudaGetSymbolAddress((void**)&A, g_A);
    cudaGetSymbolAddress((void**)&S, g_S);

    // fp16 conversions (padded [.. x 304]); fused pairs via grid.y
    {
        int t1 = BN_ROWS * (DP / 4);
        cvt_pad2_kernel<<<dim3((t1 + 255) / 256, 2), 256>>>(
            concepts, ocr, c_h, o_h, BN_ROWS, DS, DP);
        int t2 = DS * (DP / 4);
        cvt_pad2_kernel<<<dim3((t2 + 255) / 256, 2), 256>>>(
            wq, wk, wqh, wkh, DS, DS, DP);
        dim3 tg((DS + 31) / 32, NS / 32, BB);
        transpose_h_kernel<<<tg, dim3(32, 8)>>>(concepts, ct_h);
    }

    // Fused projections: z=0: Q = concepts@wq^T+bq ; z=1: K = ocr@wk^T+bk (fp16, ldc=304)
    gemm_ar_kernel<4><<<dim3(BN_ROWS / 256, 1, 2), 512, SM4>>>(
        c_h, o_h, wqh, wkh, bq, bk, nullptr, Qh, Kh,
        BN_ROWS, DS, DP, DP, /*nTiles=*/3, 0, 0, 0, 1.0f);

    // scores[b] = (Q K^T)/sqrt(D)  fp32, one CTA covers full N via 4 inner n-tiles
    gemm_ar_kernel<4><<<dim3(NS / 256, 1, BB), 512, SM4>>>(
        Qh, nullptr, Kh, nullptr, nullptr, nullptr, A, nullptr, nullptr,
        NS, NS, DP, NS, /*nTiles=*/4,
        (long long)NS * DP, (long long)NS * DP, (long long)NS * NS, INV_SQRT_D);

    // softmax -> P fp16
    softmax_h_kernel<<<BN_ROWS, 128>>>(A, Ph);

    // sem[b] = P @ concepts[b]  (B = concepts^T, K=512), MTILE=128, 3 inner n-tiles
    gemm_ar_kernel<2><<<dim3(NS / 128, 1, BB), 512, SM2>>>(
        Ph, nullptr, ct_h, nullptr, nullptr, nullptr, S, nullptr, nullptr,
        NS, DS, NS, DS, /*nTiles=*/3,
        (long long)NS * NS, (long long)DS * NS, (long long)NS * DS, 1.0f);

    // mask + residual + LayerNorm
    epilogue_kernel<<<BN_ROWS, 128>>>(S, ocr, mask, lnw, lnb, out);

    (void)in_sizes; (void)n_in; (void)out_size;
}